// round 1
// baseline (speedup 1.0000x reference)
#include <cuda_runtime.h>
#include <cuda_bf16.h>
#include <cstdint>

// Problem constants (PointNetFeaturePropagation_5609227289179)
#define BB   4
#define NN   16384
#define SS   4096
#define D1   128
#define D2   256
#define C1   384      // D1 + D2
#define O1   256      // mlp[0]
#define O2   128      // mlp[1]
#define MTOT (BB*NN)  // 65536

// ---------------------------------------------------------------------------
// Scratch (device globals — no allocation allowed)
// ---------------------------------------------------------------------------
__device__ __align__(16) float g_p2w[SS * BB * O1];   // points2 @ W1b^T  : [B*S, 256] 16MB
__device__ __align__(16) float g_h1 [MTOT * O1];      // layer1 pre-BN    : [65536, 256] 64MB
__device__ __align__(16) int   g_idx[MTOT * 3];
__device__ __align__(16) float g_w  [MTOT * 3];
__device__ float g_sum1[O1], g_sq1[O1], g_a1[O1], g_c1[O1];
__device__ float g_sum2[O2], g_sq2[O2], g_a2[O2], g_c2[O2];

// ---------------------------------------------------------------------------
// zero BN accumulators (re-run every launch / graph replay)
// ---------------------------------------------------------------------------
__global__ void zero_stats_kernel() {
    int t = threadIdx.x;
    if (t < O1) { g_sum1[t] = 0.f; g_sq1[t] = 0.f; }
    if (t < O2) { g_sum2[t] = 0.f; g_sq2[t] = 0.f; }
}

// ---------------------------------------------------------------------------
// 3-NN: for each query point find the 3 nearest of S=4096 points.
// Ordering key d' = ||p||^2 - 2 q.p (equal ordering to true sq-dist).
// True distance recovered as max(d' + ||q||^2, 0) for the weights.
// ---------------------------------------------------------------------------
__global__ __launch_bounds__(256) void knn_kernel(
    const float* __restrict__ xyz1, const float* __restrict__ xyz2,
    int* __restrict__ oidx, float* __restrict__ ow)
{
    __shared__ float4 sp[2048];
    const int b = blockIdx.y;
    const int n = blockIdx.x * 256 + threadIdx.x;

    const float* q = xyz1 + ((size_t)b * NN + n) * 3;
    const float qx = q[0], qy = q[1], qz = q[2];

    float b0v = 1e30f, b1v = 1e30f, b2v = 1e30f;
    int   i0 = 0, i1 = 0, i2 = 0;

    for (int c0 = 0; c0 < SS; c0 += 2048) {
        __syncthreads();
        #pragma unroll
        for (int r = 0; r < 8; r++) {
            int s = threadIdx.x + r * 256;
            const float* p = xyz2 + ((size_t)b * SS + c0 + s) * 3;
            float x = p[0], y = p[1], z = p[2];
            sp[s] = make_float4(x, y, z, x * x + y * y + z * z);
        }
        __syncthreads();

        #pragma unroll 4
        for (int j = 0; j < 2048; j++) {
            float4 p = sp[j];
            float dot = qx * p.x;
            dot = fmaf(qy, p.y, dot);
            dot = fmaf(qz, p.z, dot);
            float d = fmaf(dot, -2.f, p.w);
            if (d < b2v) {
                int s = c0 + j;
                if (d < b1v) {
                    b2v = b1v; i2 = i1;
                    if (d < b0v) { b1v = b0v; i1 = i0; b0v = d; i0 = s; }
                    else         { b1v = d;  i1 = s; }
                } else { b2v = d; i2 = s; }
            }
        }
    }

    const float qn = qx * qx + qy * qy + qz * qz;
    float d0 = fmaxf(b0v + qn, 0.f);
    float d1 = fmaxf(b1v + qn, 0.f);
    float d2 = fmaxf(b2v + qn, 0.f);
    float r0 = 1.f / (d0 + 1e-8f);
    float r1 = 1.f / (d1 + 1e-8f);
    float r2 = 1.f / (d2 + 1e-8f);
    float inv = 1.f / (r0 + r1 + r2);

    size_t o = ((size_t)b * NN + n) * 3;
    oidx[o + 0] = i0; oidx[o + 1] = i1; oidx[o + 2] = i2;
    ow[o + 0] = r0 * inv; ow[o + 1] = r1 * inv; ow[o + 2] = r2 * inv;
}

// ---------------------------------------------------------------------------
// Tiled SGEMM:  C[M,N] = A[M,K] @ Bw[N,K]^T   (both K-contiguous)
// BM=BN=128, BK=16, 256 threads, 8x8 microtile.
// MODE 0: plain                       (P2W = points2 @ W1b^T)
// MODE 1: epilogue += bias + sum_j w_j * p2w[idx_j]   (layer-1 out)
// MODE 2: A transformed on load: relu(a1*A + c1); epilogue += bias  (layer-2)
// ---------------------------------------------------------------------------
template<int MODE>
__global__ __launch_bounds__(256, 2) void sgemm_kernel(
    const float* __restrict__ A, int lda,
    const float* __restrict__ Bw, int ldb,
    int K,
    float* __restrict__ C, int ldc,
    const float* __restrict__ bias,
    const float* __restrict__ bn_a, const float* __restrict__ bn_c,
    const float* __restrict__ p2w, const int* __restrict__ gidx,
    const float* __restrict__ gw)
{
    __shared__ float As[16][128];
    __shared__ float Bs[16][128];
    __shared__ float s_extra[(MODE == 0) ? 1 : 768];

    const int tid = threadIdx.x;
    const int m0 = blockIdx.y * 128;
    const int n0 = blockIdx.x * 128;

    if (MODE == 1) {
        int*   si = (int*)s_extra;
        for (int i = tid; i < 384; i += 256) {
            si[i]          = gidx[(size_t)m0 * 3 + i];
            s_extra[384+i] = gw  [(size_t)m0 * 3 + i];
        }
    }
    if (MODE == 2) {
        for (int i = tid; i < K; i += 256) {
            s_extra[i]       = bn_a[i];
            s_extra[384 + i] = bn_c[i];
        }
    }
    __syncthreads();

    const int ar = tid >> 2;        // 0..63
    const int ak = (tid & 3) * 4;   // 0,4,8,12
    const int tx = tid & 15, ty = tid >> 4;
    const int cm = ty * 8, cn = tx * 8;

    float acc[8][8];
    #pragma unroll
    for (int i = 0; i < 8; i++)
        #pragma unroll
        for (int j = 0; j < 8; j++) acc[i][j] = 0.f;

    for (int k0 = 0; k0 < K; k0 += 16) {
        float4 va0 = *(const float4*)&A [(size_t)(m0 + ar     ) * lda + k0 + ak];
        float4 va1 = *(const float4*)&A [(size_t)(m0 + ar + 64) * lda + k0 + ak];
        float4 vb0 = *(const float4*)&Bw[(size_t)(n0 + ar     ) * ldb + k0 + ak];
        float4 vb1 = *(const float4*)&Bw[(size_t)(n0 + ar + 64) * ldb + k0 + ak];

        if (MODE == 2) {
            int kg = k0 + ak;
            va0.x = fmaxf(fmaf(va0.x, s_extra[kg+0], s_extra[384+kg+0]), 0.f);
            va0.y = fmaxf(fmaf(va0.y, s_extra[kg+1], s_extra[384+kg+1]), 0.f);
            va0.z = fmaxf(fmaf(va0.z, s_extra[kg+2], s_extra[384+kg+2]), 0.f);
            va0.w = fmaxf(fmaf(va0.w, s_extra[kg+3], s_extra[384+kg+3]), 0.f);
            va1.x = fmaxf(fmaf(va1.x, s_extra[kg+0], s_extra[384+kg+0]), 0.f);
            va1.y = fmaxf(fmaf(va1.y, s_extra[kg+1], s_extra[384+kg+1]), 0.f);
            va1.z = fmaxf(fmaf(va1.z, s_extra[kg+2], s_extra[384+kg+2]), 0.f);
            va1.w = fmaxf(fmaf(va1.w, s_extra[kg+3], s_extra[384+kg+3]), 0.f);
        }
        __syncthreads();
        As[ak+0][ar] = va0.x; As[ak+1][ar] = va0.y; As[ak+2][ar] = va0.z; As[ak+3][ar] = va0.w;
        As[ak+0][ar+64] = va1.x; As[ak+1][ar+64] = va1.y; As[ak+2][ar+64] = va1.z; As[ak+3][ar+64] = va1.w;
        Bs[ak+0][ar] = vb0.x; Bs[ak+1][ar] = vb0.y; Bs[ak+2][ar] = vb0.z; Bs[ak+3][ar] = vb0.w;
        Bs[ak+0][ar+64] = vb1.x; Bs[ak+1][ar+64] = vb1.y; Bs[ak+2][ar+64] = vb1.z; Bs[ak+3][ar+64] = vb1.w;
        __syncthreads();

        #pragma unroll
        for (int kk = 0; kk < 16; kk++) {
            float a_r[8], b_r[8];
            *(float4*)&a_r[0] = *(const float4*)&As[kk][cm];
            *(float4*)&a_r[4] = *(const float4*)&As[kk][cm + 4];
            *(float4*)&b_r[0] = *(const float4*)&Bs[kk][cn];
            *(float4*)&b_r[4] = *(const float4*)&Bs[kk][cn + 4];
            #pragma unroll
            for (int i = 0; i < 8; i++)
                #pragma unroll
                for (int j = 0; j < 8; j++)
                    acc[i][j] = fmaf(a_r[i], b_r[j], acc[i][j]);
        }
        __syncthreads();
    }

    // epilogue
    float bv[8];
    if (MODE != 0) {
        #pragma unroll
        for (int j = 0; j < 8; j++) bv[j] = bias[n0 + cn + j];
    }

    #pragma unroll
    for (int i = 0; i < 8; i++) {
        const int lm = cm + i;
        float outv[8];
        if (MODE == 1) {
            const int bidx = m0 >> 14;   // batch of this row-band (128 | 16384)
            const int*   si  = (const int*)s_extra;
            const float* swt = s_extra + 384;
            float w0 = swt[lm*3+0], w1 = swt[lm*3+1], w2 = swt[lm*3+2];
            const float* P0 = p2w + ((size_t)(bidx * SS + si[lm*3+0])) * O1 + n0 + cn;
            const float* P1 = p2w + ((size_t)(bidx * SS + si[lm*3+1])) * O1 + n0 + cn;
            const float* P2 = p2w + ((size_t)(bidx * SS + si[lm*3+2])) * O1 + n0 + cn;
            float4 p0a = *(const float4*)P0, p0b = *(const float4*)(P0+4);
            float4 p1a = *(const float4*)P1, p1b = *(const float4*)(P1+4);
            float4 p2a = *(const float4*)P2, p2b = *(const float4*)(P2+4);
            const float* q0 = &p0a.x; const float* q1 = &p1a.x; const float* q2 = &p2a.x;
            #pragma unroll
            for (int j = 0; j < 4; j++)
                outv[j] = acc[i][j] + bv[j] + w0*q0[j] + w1*q1[j] + w2*q2[j];
            q0 = &p0b.x; q1 = &p1b.x; q2 = &p2b.x;
            #pragma unroll
            for (int j = 0; j < 4; j++)
                outv[4+j] = acc[i][4+j] + bv[4+j] + w0*q0[j] + w1*q1[j] + w2*q2[j];
        } else {
            #pragma unroll
            for (int j = 0; j < 8; j++)
                outv[j] = acc[i][j] + ((MODE != 0) ? bv[j] : 0.f);
        }
        float* Cp = C + (size_t)(m0 + lm) * ldc + n0 + cn;
        *(float4*)Cp       = make_float4(outv[0], outv[1], outv[2], outv[3]);
        *(float4*)(Cp + 4) = make_float4(outv[4], outv[5], outv[6], outv[7]);
    }
}

// ---------------------------------------------------------------------------
// BN batch statistics: per-channel sum / sumsq over 128-row chunks, atomics.
// blockDim.x == C (channel count). Grid = MTOT/128.
// ---------------------------------------------------------------------------
__global__ void stats_kernel(const float* __restrict__ H, int Cn,
                             float* __restrict__ gsum, float* __restrict__ gsq)
{
    const int c = threadIdx.x;
    const size_t r0 = (size_t)blockIdx.x * 128;
    const float* p = H + r0 * Cn + c;
    float s = 0.f, q = 0.f;
    #pragma unroll 4
    for (int r = 0; r < 128; r++) {
        float v = p[(size_t)r * Cn];
        s += v;
        q = fmaf(v, v, q);
    }
    atomicAdd(&gsum[c], s);
    atomicAdd(&gsq[c], q);
}

__global__ void finalize_kernel(const float* __restrict__ sum, const float* __restrict__ sq,
                                const float* __restrict__ gamma, const float* __restrict__ beta,
                                float* __restrict__ a_out, float* __restrict__ c_out)
{
    const int c = threadIdx.x;
    const float Minv = 1.f / (float)MTOT;
    float mean = sum[c] * Minv;
    float var  = fmaf(-mean, mean, sq[c] * Minv);   // biased variance
    float s = gamma[c] * rsqrtf(var + 1e-5f);
    a_out[c] = s;
    c_out[c] = fmaf(-mean, s, beta[c]);
}

// final in-place BN+ReLU over the output [MTOT, 128]
__global__ void bnrelu_kernel(float* __restrict__ out,
                              const float* __restrict__ a, const float* __restrict__ c)
{
    const size_t i = (size_t)blockIdx.x * blockDim.x + threadIdx.x;  // float4 index
    float4 v = ((float4*)out)[i];
    const int cb = (int)((i * 4) & (O2 - 1));
    v.x = fmaxf(fmaf(v.x, a[cb + 0], c[cb + 0]), 0.f);
    v.y = fmaxf(fmaf(v.y, a[cb + 1], c[cb + 1]), 0.f);
    v.z = fmaxf(fmaf(v.z, a[cb + 2], c[cb + 2]), 0.f);
    v.w = fmaxf(fmaf(v.w, a[cb + 3], c[cb + 3]), 0.f);
    ((float4*)out)[i] = v;
}

// ---------------------------------------------------------------------------
extern "C" void kernel_launch(void* const* d_in, const int* in_sizes, int n_in,
                              void* d_out, int out_size)
{
    const float* xyz1    = (const float*)d_in[0];
    const float* xyz2    = (const float*)d_in[1];
    const float* points1 = (const float*)d_in[2];
    const float* points2 = (const float*)d_in[3];
    const float* W1      = (const float*)d_in[4];
    const float* b1      = (const float*)d_in[5];
    const float* g1      = (const float*)d_in[6];
    const float* be1     = (const float*)d_in[7];
    const float* W2      = (const float*)d_in[8];
    const float* b2      = (const float*)d_in[9];
    const float* g2      = (const float*)d_in[10];
    const float* be2     = (const float*)d_in[11];
    float* out = (float*)d_out;

    float *p2w, *h1, *wp, *sum1, *sq1, *a1, *c1, *sum2, *sq2, *a2, *c2;
    int* idxp;
    cudaGetSymbolAddress((void**)&p2w,  g_p2w);
    cudaGetSymbolAddress((void**)&h1,   g_h1);
    cudaGetSymbolAddress((void**)&idxp, g_idx);
    cudaGetSymbolAddress((void**)&wp,   g_w);
    cudaGetSymbolAddress((void**)&sum1, g_sum1);
    cudaGetSymbolAddress((void**)&sq1,  g_sq1);
    cudaGetSymbolAddress((void**)&a1,   g_a1);
    cudaGetSymbolAddress((void**)&c1,   g_c1);
    cudaGetSymbolAddress((void**)&sum2, g_sum2);
    cudaGetSymbolAddress((void**)&sq2,  g_sq2);
    cudaGetSymbolAddress((void**)&a2,   g_a2);
    cudaGetSymbolAddress((void**)&c2,   g_c2);

    // 1. zero BN accumulators
    zero_stats_kernel<<<1, 256>>>();

    // 2. 3-NN indices + weights
    knn_kernel<<<dim3(NN / 256, BB), 256>>>(xyz1, xyz2, idxp, wp);

    // 3. P2W = points2 @ W1b^T   (W1 columns 128..383), [B*S, 256]
    sgemm_kernel<0><<<dim3(O1 / 128, (BB * SS) / 128), 256>>>(
        points2, D2, W1 + D1, C1, D2, p2w, O1,
        nullptr, nullptr, nullptr, nullptr, nullptr, nullptr);

    // 4. h1 = points1 @ W1a^T + b1 + sum_j w_j * P2W[idx_j]
    sgemm_kernel<1><<<dim3(O1 / 128, MTOT / 128), 256>>>(
        points1, D1, W1, C1, D1, h1, O1,
        b1, nullptr, nullptr, p2w, idxp, wp);

    // 5/6. BN1 stats + affine coefficients
    stats_kernel<<<MTOT / 128, O1>>>(h1, O1, sum1, sq1);
    finalize_kernel<<<1, O1>>>(sum1, sq1, g1, be1, a1, c1);

    // 7. out = relu(a1*h1 + c1) @ W2^T + b2   (BN1+ReLU fused into A load)
    sgemm_kernel<2><<<dim3(O2 / 128, MTOT / 128), 256>>>(
        h1, O1, W2, O1, O1, out, O2,
        b2, a1, c1, nullptr, nullptr, nullptr);

    // 8/9. BN2 stats + coefficients
    stats_kernel<<<MTOT / 128, O2>>>(out, O2, sum2, sq2);
    finalize_kernel<<<1, O2>>>(sum2, sq2, g2, be2, a2, c2);

    // 10. in-place BN2 + ReLU
    bnrelu_kernel<<<(MTOT * O2 / 4) / 256, 256>>>(out, a2, c2);
}

// round 4
// speedup vs baseline: 1.2864x; 1.2864x over previous
#include <cuda_runtime.h>
#include <cuda_bf16.h>
#include <cstdint>

// Problem constants (PointNetFeaturePropagation_5609227289179)
#define BB   4
#define NN   16384
#define SS   4096
#define D1   128
#define D2   256
#define C1   384
#define O1   256
#define O2   128
#define MTOT (BB*NN)   // 65536

// ---------------------------------------------------------------------------
// Scratch (device globals — no allocation allowed)
// ---------------------------------------------------------------------------
__device__ __align__(16) float g_p2w[BB * SS * O1];   // points2 @ W1b^T [16384,256]
__device__ __align__(16) float g_h1 [MTOT * O1];      // layer1 pre-BN   [65536,256]
__device__ __align__(16) int   g_idx[MTOT * 3];
__device__ __align__(16) float g_w  [MTOT * 3];
__device__ __align__(16) __nv_bfloat16 g_b0h[O1 * D2], g_b0l[O1 * D2];  // W1b split
__device__ __align__(16) __nv_bfloat16 g_b1h[O1 * D1], g_b1l[O1 * D1];  // W1a split
__device__ __align__(16) __nv_bfloat16 g_b2h[O2 * O1], g_b2l[O2 * O1];  // W2 split
__device__ float g_sum1[O1], g_sq1[O1], g_a1[O1], g_c1[O1];
__device__ float g_sum2[O2], g_sq2[O2], g_a2[O2], g_c2[O2];

// ---------------------------------------------------------------------------
__global__ void zero_stats_kernel() {
    int t = threadIdx.x;
    if (t < O1) { g_sum1[t] = 0.f; g_sq1[t] = 0.f; }
    if (t < O2) { g_sum2[t] = 0.f; g_sq2[t] = 0.f; }
}

// Pre-split weights into bf16 hi/lo
__global__ void prep_weights_kernel(const float* __restrict__ W1,
                                    const float* __restrict__ W2) {
    int idx = blockIdx.x * 256 + threadIdx.x;
    if (idx < O1 * C1) {
        int o = idx / C1, k = idx - o * C1;
        float v = W1[idx];
        __nv_bfloat16 h = __float2bfloat16(v);
        __nv_bfloat16 l = __float2bfloat16(v - __bfloat162float(h));
        if (k < D1) { g_b1h[o * D1 + k] = h; g_b1l[o * D1 + k] = l; }
        else        { g_b0h[o * D2 + k - D1] = h; g_b0l[o * D2 + k - D1] = l; }
    }
    if (idx < O2 * O1) {
        float v = W2[idx];
        __nv_bfloat16 h = __float2bfloat16(v);
        __nv_bfloat16 l = __float2bfloat16(v - __bfloat162float(h));
        g_b2h[idx] = h; g_b2l[idx] = l;
    }
}

// ---------------------------------------------------------------------------
// 3-NN
// ---------------------------------------------------------------------------
__global__ __launch_bounds__(256) void knn_kernel(
    const float* __restrict__ xyz1, const float* __restrict__ xyz2,
    int* __restrict__ oidx, float* __restrict__ ow)
{
    __shared__ float4 sp[2048];
    const int b = blockIdx.y;
    const int n = blockIdx.x * 256 + threadIdx.x;

    const float* q = xyz1 + ((size_t)b * NN + n) * 3;
    const float qx = q[0], qy = q[1], qz = q[2];

    float b0v = 1e30f, b1v = 1e30f, b2v = 1e30f;
    int   i0 = 0, i1 = 0, i2 = 0;

    for (int c0 = 0; c0 < SS; c0 += 2048) {
        __syncthreads();
        #pragma unroll
        for (int r = 0; r < 8; r++) {
            int s = threadIdx.x + r * 256;
            const float* p = xyz2 + ((size_t)b * SS + c0 + s) * 3;
            float x = p[0], y = p[1], z = p[2];
            sp[s] = make_float4(x, y, z, x * x + y * y + z * z);
        }
        __syncthreads();

        #pragma unroll 4
        for (int j = 0; j < 2048; j++) {
            float4 p = sp[j];
            float dot = qx * p.x;
            dot = fmaf(qy, p.y, dot);
            dot = fmaf(qz, p.z, dot);
            float d = fmaf(dot, -2.f, p.w);
            if (d < b2v) {
                int s = c0 + j;
                if (d < b1v) {
                    b2v = b1v; i2 = i1;
                    if (d < b0v) { b1v = b0v; i1 = i0; b0v = d; i0 = s; }
                    else         { b1v = d;  i1 = s; }
                } else { b2v = d; i2 = s; }
            }
        }
    }

    const float qn = qx * qx + qy * qy + qz * qz;
    float d0 = fmaxf(b0v + qn, 0.f);
    float d1 = fmaxf(b1v + qn, 0.f);
    float d2 = fmaxf(b2v + qn, 0.f);
    float r0 = 1.f / (d0 + 1e-8f);
    float r1 = 1.f / (d1 + 1e-8f);
    float r2 = 1.f / (d2 + 1e-8f);
    float inv = 1.f / (r0 + r1 + r2);

    size_t o = ((size_t)b * NN + n) * 3;
    oidx[o + 0] = i0; oidx[o + 1] = i1; oidx[o + 2] = i2;
    ow[o + 0] = r0 * inv; ow[o + 1] = r1 * inv; ow[o + 2] = r2 * inv;
}

// ---------------------------------------------------------------------------
// bf16-split tensor-core GEMM via mma.sync.m16n8k16 (sm_80-compatible PTX):
//   C[M,N] = A[M,K] @ Bw[N,K]^T,  A fp32 split to (Ah,Al), Bw pre-split.
//   D = Ah*Bh + Al*Bh + Ah*Bl in fp32 accumulators (rel err ~1e-5).
// CTA tile 128x64, BK=32, 8 warps (4x2) of 32x32 warp tiles. Double-buffered
// smem (80B row stride -> verified conflict-free fragment LDS).
// MODE 0: plain        MODE 1: +bias + 3NN-gather     MODE 2: BN+ReLU on A, +bias
// ---------------------------------------------------------------------------
#define STRB  80          // smem row stride bytes (40 bf16)
#define A_T   10240       // 128*80
#define B_T   5120        // 64*80
#define STGB  30720       // per-stage bytes: Ah,Al,Bh,Bl
#define SM_BIAS 61440
#define SM_SA   61696
#define SM_SC   63232
#define SM_SZ   64768

__device__ __forceinline__ void mma16816(float* d, const uint32_t* a, const uint32_t* b) {
    asm volatile(
        "mma.sync.aligned.m16n8k16.row.col.f32.bf16.bf16.f32 "
        "{%0,%1,%2,%3}, {%4,%5,%6,%7}, {%8,%9}, {%0,%1,%2,%3};"
        : "+f"(d[0]), "+f"(d[1]), "+f"(d[2]), "+f"(d[3])
        : "r"(a[0]), "r"(a[1]), "r"(a[2]), "r"(a[3]), "r"(b[0]), "r"(b[1]));
}
__device__ __forceinline__ uint32_t pack_hi2(float x, float y) {
    uint16_t hx = __bfloat16_as_ushort(__float2bfloat16(x));
    uint16_t hy = __bfloat16_as_ushort(__float2bfloat16(y));
    return (uint32_t)hx | ((uint32_t)hy << 16);
}
__device__ __forceinline__ uint32_t pack_lo2(float x, float y) {
    float hx = __bfloat162float(__float2bfloat16(x));
    float hy = __bfloat162float(__float2bfloat16(y));
    uint16_t lx = __bfloat16_as_ushort(__float2bfloat16(x - hx));
    uint16_t ly = __bfloat16_as_ushort(__float2bfloat16(y - hy));
    return (uint32_t)lx | ((uint32_t)ly << 16);
}

template<int MODE, int KTOT>
__global__ __launch_bounds__(256, 2) void mma_gemm(
    const float* __restrict__ A, int lda,
    const __nv_bfloat16* __restrict__ Bh, const __nv_bfloat16* __restrict__ Bl,
    float* __restrict__ C, int ldc,
    const float* __restrict__ bias,
    const float* __restrict__ bn_a, const float* __restrict__ bn_c,
    const float* __restrict__ p2w, const int* __restrict__ gidx,
    const float* __restrict__ gw)
{
    extern __shared__ char sm[];
    const int tid = threadIdx.x;
    const int m0 = blockIdx.y * 128;
    const int n0 = blockIdx.x * 64;

    float* sbias = (float*)(sm + SM_BIAS);
    float* sa    = (float*)(sm + SM_SA);
    float* sc    = (float*)(sm + SM_SC);
    if (MODE != 0 && tid < 64) sbias[tid] = bias[n0 + tid];
    if (MODE == 2 && tid < KTOT) { sa[tid] = bn_a[tid]; sc[tid] = bn_c[tid]; }
    __syncthreads();

    // gmem->reg prefetch mapping
    const int ra = tid >> 1, ka = (tid & 1) * 16;   // A: 128 rows x 32 k
    const int rb = tid >> 2, kb2 = (tid & 3) * 8;   // B: 64 rows x 32 k

    float4 av[4];
    uint4 bhv, blv;

    auto loadG = [&](int k0) {
        const float* ap = A + (size_t)(m0 + ra) * lda + k0 + ka;
        #pragma unroll
        for (int i = 0; i < 4; i++) av[i] = *(const float4*)(ap + i * 4);
        bhv = *(const uint4*)(Bh + (size_t)(n0 + rb) * KTOT + k0 + kb2);
        blv = *(const uint4*)(Bl + (size_t)(n0 + rb) * KTOT + k0 + kb2);
    };
    auto storeS = [&](int st, int k0) {
        char* base = sm + st * STGB;
        #pragma unroll
        for (int i = 0; i < 4; i++) {
            float4 v = av[i];
            if (MODE == 2) {
                int kg = k0 + ka + i * 4;
                v.x = fmaxf(fmaf(v.x, sa[kg + 0], sc[kg + 0]), 0.f);
                v.y = fmaxf(fmaf(v.y, sa[kg + 1], sc[kg + 1]), 0.f);
                v.z = fmaxf(fmaf(v.z, sa[kg + 2], sc[kg + 2]), 0.f);
                v.w = fmaxf(fmaf(v.w, sa[kg + 3], sc[kg + 3]), 0.f);
            }
            uint2 h2 = make_uint2(pack_hi2(v.x, v.y), pack_hi2(v.z, v.w));
            uint2 l2 = make_uint2(pack_lo2(v.x, v.y), pack_lo2(v.z, v.w));
            int ob = ra * STRB + (ka + i * 4) * 2;
            *(uint2*)(base + ob)       = h2;
            *(uint2*)(base + A_T + ob) = l2;
        }
        {
            int ob = rb * STRB + kb2 * 2;
            char* bh_ = base + 2 * A_T + ob;
            char* bl_ = base + 2 * A_T + B_T + ob;
            *(uint2*)(bh_)     = make_uint2(bhv.x, bhv.y);
            *(uint2*)(bh_ + 8) = make_uint2(bhv.z, bhv.w);
            *(uint2*)(bl_)     = make_uint2(blv.x, blv.y);
            *(uint2*)(bl_ + 8) = make_uint2(blv.z, blv.w);
        }
    };

    const int wid = tid >> 5, l = tid & 31;
    const int wm = (wid >> 1) * 32, wn = (wid & 1) * 32;
    const int lr = l >> 2, lc = l & 3;

    float acc[2][4][4];
    #pragma unroll
    for (int mi = 0; mi < 2; mi++)
        #pragma unroll
        for (int ni = 0; ni < 4; ni++)
            #pragma unroll
            for (int j = 0; j < 4; j++) acc[mi][ni][j] = 0.f;

    auto comp = [&](int st) {
        const char* base = sm + st * STGB;
        #pragma unroll
        for (int ks = 0; ks < 2; ks++) {
            const int kb = ks * 32 + lc * 4;   // byte offset of this thread's k pair
            uint32_t ah[2][4], al[2][4], bh[4][2], bl[4][2];
            #pragma unroll
            for (int mi = 0; mi < 2; mi++) {
                const char* p = base + (wm + mi * 16 + lr) * STRB + kb;
                ah[mi][0] = *(const uint32_t*)(p);
                ah[mi][1] = *(const uint32_t*)(p + 8 * STRB);
                ah[mi][2] = *(const uint32_t*)(p + 16);
                ah[mi][3] = *(const uint32_t*)(p + 8 * STRB + 16);
                const char* q = p + A_T;
                al[mi][0] = *(const uint32_t*)(q);
                al[mi][1] = *(const uint32_t*)(q + 8 * STRB);
                al[mi][2] = *(const uint32_t*)(q + 16);
                al[mi][3] = *(const uint32_t*)(q + 8 * STRB + 16);
            }
            #pragma unroll
            for (int ni = 0; ni < 4; ni++) {
                const char* p = base + 2 * A_T + (wn + ni * 8 + lr) * STRB + kb;
                bh[ni][0] = *(const uint32_t*)(p);
                bh[ni][1] = *(const uint32_t*)(p + 16);
                const char* q = p + B_T;
                bl[ni][0] = *(const uint32_t*)(q);
                bl[ni][1] = *(const uint32_t*)(q + 16);
            }
            #pragma unroll
            for (int mi = 0; mi < 2; mi++)
                #pragma unroll
                for (int ni = 0; ni < 4; ni++) {
                    mma16816(acc[mi][ni], ah[mi], bh[ni]);
                    mma16816(acc[mi][ni], al[mi], bh[ni]);
                    mma16816(acc[mi][ni], ah[mi], bl[ni]);
                }
        }
    };

    constexpr int nch = KTOT / 32;
    loadG(0);
    storeS(0, 0);
    __syncthreads();
    #pragma unroll
    for (int kc = 0; kc < nch; kc++) {
        if (kc + 1 < nch) loadG((kc + 1) * 32);
        comp(kc & 1);
        if (kc + 1 < nch) {
            storeS((kc + 1) & 1, (kc + 1) * 32);
            __syncthreads();
        }
    }

    // --- epilogue: accumulators -> gmem with fused bias / gather
    #pragma unroll
    for (int mi = 0; mi < 2; mi++) {
        #pragma unroll
        for (int half = 0; half < 2; half++) {
            const int gm = m0 + wm + mi * 16 + half * 8 + lr;
            const float *P0 = nullptr, *P1 = nullptr, *P2 = nullptr;
            float w0 = 0.f, w1 = 0.f, w2 = 0.f;
            if (MODE == 1) {
                const int bb_ = gm >> 14;                // NN = 16384
                int i0 = gidx[gm * 3 + 0], i1 = gidx[gm * 3 + 1], i2 = gidx[gm * 3 + 2];
                w0 = gw[gm * 3 + 0]; w1 = gw[gm * 3 + 1]; w2 = gw[gm * 3 + 2];
                P0 = p2w + ((size_t)bb_ * SS + i0) * O1 + n0;
                P1 = p2w + ((size_t)bb_ * SS + i1) * O1 + n0;
                P2 = p2w + ((size_t)bb_ * SS + i2) * O1 + n0;
            }
            float* Cp = C + (size_t)gm * ldc + n0;
            #pragma unroll
            for (int ni = 0; ni < 4; ni++) {
                const int col = wn + ni * 8 + lc * 2;
                float x = acc[mi][ni][half * 2 + 0];
                float y = acc[mi][ni][half * 2 + 1];
                if (MODE != 0) { x += sbias[col]; y += sbias[col + 1]; }
                if (MODE == 1) {
                    float2 q0 = *(const float2*)(P0 + col);
                    float2 q1 = *(const float2*)(P1 + col);
                    float2 q2 = *(const float2*)(P2 + col);
                    x += w0 * q0.x + w1 * q1.x + w2 * q2.x;
                    y += w0 * q0.y + w1 * q1.y + w2 * q2.y;
                }
                *(float2*)(Cp + col) = make_float2(x, y);
            }
        }
    }
}

// ---------------------------------------------------------------------------
// BN stats / finalize / apply
// ---------------------------------------------------------------------------
__global__ void stats_kernel(const float* __restrict__ H, int Cn,
                             float* __restrict__ gsum, float* __restrict__ gsq)
{
    const int c = threadIdx.x;
    const size_t r0 = (size_t)blockIdx.x * 128;
    const float* p = H + r0 * Cn + c;
    float s = 0.f, q = 0.f;
    #pragma unroll 4
    for (int r = 0; r < 128; r++) {
        float v = p[(size_t)r * Cn];
        s += v;
        q = fmaf(v, v, q);
    }
    atomicAdd(&gsum[c], s);
    atomicAdd(&gsq[c], q);
}

__global__ void finalize_kernel(const float* __restrict__ sum, const float* __restrict__ sq,
                                const float* __restrict__ gamma, const float* __restrict__ beta,
                                float* __restrict__ a_out, float* __restrict__ c_out)
{
    const int c = threadIdx.x;
    const float Minv = 1.f / (float)MTOT;
    float mean = sum[c] * Minv;
    float var  = fmaf(-mean, mean, sq[c] * Minv);
    float s = gamma[c] * rsqrtf(var + 1e-5f);
    a_out[c] = s;
    c_out[c] = fmaf(-mean, s, beta[c]);
}

__global__ void bnrelu_kernel(float* __restrict__ out,
                              const float* __restrict__ a, const float* __restrict__ c)
{
    const size_t i = (size_t)blockIdx.x * blockDim.x + threadIdx.x;
    float4 v = ((float4*)out)[i];
    const int cb = (int)((i * 4) & (O2 - 1));
    v.x = fmaxf(fmaf(v.x, a[cb + 0], c[cb + 0]), 0.f);
    v.y = fmaxf(fmaf(v.y, a[cb + 1], c[cb + 1]), 0.f);
    v.z = fmaxf(fmaf(v.z, a[cb + 2], c[cb + 2]), 0.f);
    v.w = fmaxf(fmaf(v.w, a[cb + 3], c[cb + 3]), 0.f);
    ((float4*)out)[i] = v;
}

// ---------------------------------------------------------------------------
extern "C" void kernel_launch(void* const* d_in, const int* in_sizes, int n_in,
                              void* d_out, int out_size)
{
    const float* xyz1    = (const float*)d_in[0];
    const float* xyz2    = (const float*)d_in[1];
    const float* points1 = (const float*)d_in[2];
    const float* points2 = (const float*)d_in[3];
    const float* W1      = (const float*)d_in[4];
    const float* b1      = (const float*)d_in[5];
    const float* g1      = (const float*)d_in[6];
    const float* be1     = (const float*)d_in[7];
    const float* W2      = (const float*)d_in[8];
    const float* b2      = (const float*)d_in[9];
    const float* g2      = (const float*)d_in[10];
    const float* be2     = (const float*)d_in[11];
    float* out = (float*)d_out;

    float *p2w, *h1, *wp, *sum1, *sq1, *a1, *c1, *sum2, *sq2, *a2, *c2;
    int* idxp;
    __nv_bfloat16 *b0h, *b0l, *b1h, *b1l, *b2h, *b2l;
    cudaGetSymbolAddress((void**)&p2w,  g_p2w);
    cudaGetSymbolAddress((void**)&h1,   g_h1);
    cudaGetSymbolAddress((void**)&idxp, g_idx);
    cudaGetSymbolAddress((void**)&wp,   g_w);
    cudaGetSymbolAddress((void**)&sum1, g_sum1);
    cudaGetSymbolAddress((void**)&sq1,  g_sq1);
    cudaGetSymbolAddress((void**)&a1,   g_a1);
    cudaGetSymbolAddress((void**)&c1,   g_c1);
    cudaGetSymbolAddress((void**)&sum2, g_sum2);
    cudaGetSymbolAddress((void**)&sq2,  g_sq2);
    cudaGetSymbolAddress((void**)&a2,   g_a2);
    cudaGetSymbolAddress((void**)&c2,   g_c2);
    cudaGetSymbolAddress((void**)&b0h,  g_b0h);
    cudaGetSymbolAddress((void**)&b0l,  g_b0l);
    cudaGetSymbolAddress((void**)&b1h,  g_b1h);
    cudaGetSymbolAddress((void**)&b1l,  g_b1l);
    cudaGetSymbolAddress((void**)&b2h,  g_b2h);
    cudaGetSymbolAddress((void**)&b2l,  g_b2l);

    cudaFuncSetAttribute(mma_gemm<0, 256>, cudaFuncAttributeMaxDynamicSharedMemorySize, SM_SZ);
    cudaFuncSetAttribute(mma_gemm<1, 128>, cudaFuncAttributeMaxDynamicSharedMemorySize, SM_SZ);
    cudaFuncSetAttribute(mma_gemm<2, 256>, cudaFuncAttributeMaxDynamicSharedMemorySize, SM_SZ);

    // 1. zero BN accumulators + weight split
    zero_stats_kernel<<<1, 256>>>();
    prep_weights_kernel<<<(O1 * C1) / 256, 256>>>(W1, W2);

    // 2. 3-NN
    knn_kernel<<<dim3(NN / 256, BB), 256>>>(xyz1, xyz2, idxp, wp);

    // 3. P2W = points2 @ W1b^T   [B*S, 256]
    mma_gemm<0, 256><<<dim3(O1 / 64, (BB * SS) / 128), 256, SM_SZ>>>(
        points2, D2, b0h, b0l, p2w, O1,
        nullptr, nullptr, nullptr, nullptr, nullptr, nullptr);

    // 4. h1 = points1 @ W1a^T + b1 + sum_j w_j * P2W[idx_j]
    mma_gemm<1, 128><<<dim3(O1 / 64, MTOT / 128), 256, SM_SZ>>>(
        points1, D1, b1h, b1l, h1, O1,
        b1, nullptr, nullptr, p2w, idxp, wp);

    // 5. BN1 stats
    stats_kernel<<<MTOT / 128, O1>>>(h1, O1, sum1, sq1);
    finalize_kernel<<<1, O1>>>(sum1, sq1, g1, be1, a1, c1);

    // 6. out = relu(a1*h1 + c1) @ W2^T + b2
    mma_gemm<2, 256><<<dim3(O2 / 64, MTOT / 128), 256, SM_SZ>>>(
        h1, O1, b2h, b2l, out, O2,
        b2, a1, c1, nullptr, nullptr, nullptr);

    // 7. BN2 stats + apply
    stats_kernel<<<MTOT / 128, O2>>>(out, O2, sum2, sq2);
    finalize_kernel<<<1, O2>>>(sum2, sq2, g2, be2, a2, c2);
    bnrelu_kernel<<<(MTOT * O2 / 4) / 256, 256>>>(out, a2, c2);
}

// round 7
// speedup vs baseline: 1.3788x; 1.0719x over previous
#include <cuda_runtime.h>
#include <cuda_bf16.h>
#include <cstdint>

// Problem constants (PointNetFeaturePropagation_5609227289179)
#define BB   4
#define NN   16384
#define SS   4096
#define D1   128
#define D2   256
#define C1   384
#define O1   256
#define O2   128
#define MTOT (BB*NN)   // 65536

// ---------------------------------------------------------------------------
// Scratch (device globals — no allocation allowed)
// ---------------------------------------------------------------------------
__device__ __align__(16) float g_p2w[BB * SS * O1];   // points2 @ W1b^T [16384,256]
__device__ __align__(16) float g_h1 [MTOT * O1];      // layer1 pre-BN   [65536,256]
__device__ __align__(16) int   g_idx[MTOT * 3];
__device__ __align__(16) float g_w  [MTOT * 3];
__device__ __align__(16) __nv_bfloat16 g_b0h[O1 * D2], g_b0l[O1 * D2];  // W1b split
__device__ __align__(16) __nv_bfloat16 g_b1h[O1 * D1], g_b1l[O1 * D1];  // W1a split
__device__ __align__(16) __nv_bfloat16 g_b2h[O2 * O1], g_b2l[O2 * O1];  // W2 split
__device__ float g_sum1[O1], g_sq1[O1], g_a1[O1], g_c1[O1];
__device__ float g_sum2[O2], g_sq2[O2], g_a2[O2], g_c2[O2];

// ---------------------------------------------------------------------------
__global__ void zero_stats_kernel() {
    int t = threadIdx.x;
    if (t < O1) { g_sum1[t] = 0.f; g_sq1[t] = 0.f; }
    if (t < O2) { g_sum2[t] = 0.f; g_sq2[t] = 0.f; }
}

// Pre-split weights into bf16 hi/lo
__global__ void prep_weights_kernel(const float* __restrict__ W1,
                                    const float* __restrict__ W2) {
    int idx = blockIdx.x * 256 + threadIdx.x;
    if (idx < O1 * C1) {
        int o = idx / C1, k = idx - o * C1;
        float v = W1[idx];
        __nv_bfloat16 h = __float2bfloat16(v);
        __nv_bfloat16 l = __float2bfloat16(v - __bfloat162float(h));
        if (k < D1) { g_b1h[o * D1 + k] = h; g_b1l[o * D1 + k] = l; }
        else        { g_b0h[o * D2 + k - D1] = h; g_b0l[o * D2 + k - D1] = l; }
    }
    if (idx < O2 * O1) {
        float v = W2[idx];
        __nv_bfloat16 h = __float2bfloat16(v);
        __nv_bfloat16 l = __float2bfloat16(v - __bfloat162float(h));
        g_b2h[idx] = h; g_b2l[idx] = l;
    }
}

// ---------------------------------------------------------------------------
// 3-NN: ordering key d' = ||p||^2 - 2 q.p, with (-2x,-2y,-2z,||p||^2) staged
// in smem -> 3 FMA per candidate.
// ---------------------------------------------------------------------------
__global__ __launch_bounds__(256) void knn_kernel(
    const float* __restrict__ xyz1, const float* __restrict__ xyz2,
    int* __restrict__ oidx, float* __restrict__ ow)
{
    __shared__ float4 sp[2048];
    const int b = blockIdx.y;
    const int n = blockIdx.x * 256 + threadIdx.x;

    const float* q = xyz1 + ((size_t)b * NN + n) * 3;
    const float qx = q[0], qy = q[1], qz = q[2];

    float b0v = 1e30f, b1v = 1e30f, b2v = 1e30f;
    int   i0 = 0, i1 = 0, i2 = 0;

    for (int c0 = 0; c0 < SS; c0 += 2048) {
        __syncthreads();
        #pragma unroll
        for (int r = 0; r < 8; r++) {
            int s = threadIdx.x + r * 256;
            const float* p = xyz2 + ((size_t)b * SS + c0 + s) * 3;
            float x = p[0], y = p[1], z = p[2];
            sp[s] = make_float4(-2.f * x, -2.f * y, -2.f * z, x * x + y * y + z * z);
        }
        __syncthreads();

        #pragma unroll 4
        for (int j = 0; j < 2048; j++) {
            float4 p = sp[j];
            float d = fmaf(qx, p.x, fmaf(qy, p.y, fmaf(qz, p.z, p.w)));
            if (d < b2v) {
                int s = c0 + j;
                if (d < b1v) {
                    b2v = b1v; i2 = i1;
                    if (d < b0v) { b1v = b0v; i1 = i0; b0v = d; i0 = s; }
                    else         { b1v = d;  i1 = s; }
                } else { b2v = d; i2 = s; }
            }
        }
    }

    const float qn = qx * qx + qy * qy + qz * qz;
    float d0 = fmaxf(b0v + qn, 0.f);
    float d1 = fmaxf(b1v + qn, 0.f);
    float d2 = fmaxf(b2v + qn, 0.f);
    float r0 = 1.f / (d0 + 1e-8f);
    float r1 = 1.f / (d1 + 1e-8f);
    float r2 = 1.f / (d2 + 1e-8f);
    float inv = 1.f / (r0 + r1 + r2);

    size_t o = ((size_t)b * NN + n) * 3;
    oidx[o + 0] = i0; oidx[o + 1] = i1; oidx[o + 2] = i2;
    ow[o + 0] = r0 * inv; ow[o + 1] = r1 * inv; ow[o + 2] = r2 * inv;
}

// ---------------------------------------------------------------------------
// bf16-split tensor-core GEMM via mma.sync.m16n8k16 (proven R4 core):
//   C[M,N] = A[M,K] @ Bw[N,K]^T,  D = Ah*Bh + Al*Bh + Ah*Bl  (fp32 accum)
// CTA tile 128x64, BK=32, 8 warps (4x2) of 32x32. Double-buffered smem.
// MODE 0: plain   MODE 1: +bias+3NN gather (+fused stats)
// MODE 2: BN+ReLU on A, +bias (+fused stats)
// ---------------------------------------------------------------------------
#define STRB  80          // smem row stride bytes (40 bf16)
#define A_T   10240       // 128*80
#define B_T   5120        // 64*80
#define STGB  30720       // per-stage bytes: Ah,Al,Bh,Bl
#define SM_BIAS 61440
#define SM_SUM  61696
#define SM_SQ   61952
#define SM_SA   62208
#define SM_SC   63232
#define SM_SZ   64256

__device__ __forceinline__ void mma16816(float* d, const uint32_t* a, const uint32_t* b) {
    asm volatile(
        "mma.sync.aligned.m16n8k16.row.col.f32.bf16.bf16.f32 "
        "{%0,%1,%2,%3}, {%4,%5,%6,%7}, {%8,%9}, {%0,%1,%2,%3};"
        : "+f"(d[0]), "+f"(d[1]), "+f"(d[2]), "+f"(d[3])
        : "r"(a[0]), "r"(a[1]), "r"(a[2]), "r"(a[3]), "r"(b[0]), "r"(b[1]));
}
__device__ __forceinline__ uint32_t pack_hi2(float x, float y) {
    uint16_t hx = __bfloat16_as_ushort(__float2bfloat16(x));
    uint16_t hy = __bfloat16_as_ushort(__float2bfloat16(y));
    return (uint32_t)hx | ((uint32_t)hy << 16);
}
__device__ __forceinline__ uint32_t pack_lo2(float x, float y) {
    float hx = __bfloat162float(__float2bfloat16(x));
    float hy = __bfloat162float(__float2bfloat16(y));
    uint16_t lx = __bfloat16_as_ushort(__float2bfloat16(x - hx));
    uint16_t ly = __bfloat16_as_ushort(__float2bfloat16(y - hy));
    return (uint32_t)lx | ((uint32_t)ly << 16);
}

template<int MODE, int KTOT>
__global__ __launch_bounds__(256, 2) void mma_gemm(
    const float* __restrict__ A, int lda,
    const __nv_bfloat16* __restrict__ Bh, const __nv_bfloat16* __restrict__ Bl,
    float* __restrict__ C, int ldc,
    const float* __restrict__ bias,
    const float* __restrict__ bn_a, const float* __restrict__ bn_c,
    const float* __restrict__ p2w, const int* __restrict__ gidx,
    const float* __restrict__ gw,
    float* __restrict__ gsum, float* __restrict__ gsq)
{
    extern __shared__ char sm[];
    const int tid = threadIdx.x;
    const int m0 = blockIdx.y * 128;
    const int n0 = blockIdx.x * 64;

    float* sbias = (float*)(sm + SM_BIAS);
    float* ssum  = (float*)(sm + SM_SUM);
    float* ssq   = (float*)(sm + SM_SQ);
    float* sa    = (float*)(sm + SM_SA);
    float* sc    = (float*)(sm + SM_SC);
    if (MODE != 0 && tid < 64) sbias[tid] = bias[n0 + tid];
    if (MODE != 0 && tid < 128) { if (tid < 64) ssum[tid] = 0.f; else ssq[tid - 64] = 0.f; }
    if (MODE == 2 && tid < KTOT) { sa[tid] = bn_a[tid]; sc[tid] = bn_c[tid]; }
    __syncthreads();

    // gmem->reg prefetch mapping
    const int ra = tid >> 1, ka = (tid & 1) * 16;   // A: 128 rows x 32 k
    const int rb = tid >> 2, kb2 = (tid & 3) * 8;   // B: 64 rows x 32 k

    float4 av[4];
    uint4 bhv, blv;

    auto loadG = [&](int k0) {
        const float* ap = A + (size_t)(m0 + ra) * lda + k0 + ka;
        #pragma unroll
        for (int i = 0; i < 4; i++) av[i] = *(const float4*)(ap + i * 4);
        bhv = *(const uint4*)(Bh + (size_t)(n0 + rb) * KTOT + k0 + kb2);
        blv = *(const uint4*)(Bl + (size_t)(n0 + rb) * KTOT + k0 + kb2);
    };
    auto storeS = [&](int st, int k0) {
        char* base = sm + st * STGB;
        #pragma unroll
        for (int i = 0; i < 4; i++) {
            float4 v = av[i];
            if (MODE == 2) {
                int kg = k0 + ka + i * 4;
                v.x = fmaxf(fmaf(v.x, sa[kg + 0], sc[kg + 0]), 0.f);
                v.y = fmaxf(fmaf(v.y, sa[kg + 1], sc[kg + 1]), 0.f);
                v.z = fmaxf(fmaf(v.z, sa[kg + 2], sc[kg + 2]), 0.f);
                v.w = fmaxf(fmaf(v.w, sa[kg + 3], sc[kg + 3]), 0.f);
            }
            uint2 h2 = make_uint2(pack_hi2(v.x, v.y), pack_hi2(v.z, v.w));
            uint2 l2 = make_uint2(pack_lo2(v.x, v.y), pack_lo2(v.z, v.w));
            int ob = ra * STRB + (ka + i * 4) * 2;
            *(uint2*)(base + ob)       = h2;
            *(uint2*)(base + A_T + ob) = l2;
        }
        {
            int ob = rb * STRB + kb2 * 2;
            char* bh_ = base + 2 * A_T + ob;
            char* bl_ = base + 2 * A_T + B_T + ob;
            *(uint2*)(bh_)     = make_uint2(bhv.x, bhv.y);
            *(uint2*)(bh_ + 8) = make_uint2(bhv.z, bhv.w);
            *(uint2*)(bl_)     = make_uint2(blv.x, blv.y);
            *(uint2*)(bl_ + 8) = make_uint2(blv.z, blv.w);
        }
    };

    const int wid = tid >> 5, l = tid & 31;
    const int wm = (wid >> 1) * 32, wn = (wid & 1) * 32;
    const int lr = l >> 2, lc = l & 3;

    float acc[2][4][4];
    #pragma unroll
    for (int mi = 0; mi < 2; mi++)
        #pragma unroll
        for (int ni = 0; ni < 4; ni++)
            #pragma unroll
            for (int j = 0; j < 4; j++) acc[mi][ni][j] = 0.f;

    auto comp = [&](int st) {
        const char* base = sm + st * STGB;
        #pragma unroll
        for (int ks = 0; ks < 2; ks++) {
            const int kb = ks * 32 + lc * 4;   // byte offset of this thread's k pair
            uint32_t ah[2][4], al[2][4], bh[4][2], bl[4][2];
            #pragma unroll
            for (int mi = 0; mi < 2; mi++) {
                const char* p = base + (wm + mi * 16 + lr) * STRB + kb;
                ah[mi][0] = *(const uint32_t*)(p);
                ah[mi][1] = *(const uint32_t*)(p + 8 * STRB);
                ah[mi][2] = *(const uint32_t*)(p + 16);
                ah[mi][3] = *(const uint32_t*)(p + 8 * STRB + 16);
                const char* q = p + A_T;
                al[mi][0] = *(const uint32_t*)(q);
                al[mi][1] = *(const uint32_t*)(q + 8 * STRB);
                al[mi][2] = *(const uint32_t*)(q + 16);
                al[mi][3] = *(const uint32_t*)(q + 8 * STRB + 16);
            }
            #pragma unroll
            for (int ni = 0; ni < 4; ni++) {
                const char* p = base + 2 * A_T + (wn + ni * 8 + lr) * STRB + kb;
                bh[ni][0] = *(const uint32_t*)(p);
                bh[ni][1] = *(const uint32_t*)(p + 16);
                const char* q = p + B_T;
                bl[ni][0] = *(const uint32_t*)(q);
                bl[ni][1] = *(const uint32_t*)(q + 16);
            }
            #pragma unroll
            for (int mi = 0; mi < 2; mi++)
                #pragma unroll
                for (int ni = 0; ni < 4; ni++) {
                    mma16816(acc[mi][ni], ah[mi], bh[ni]);
                    mma16816(acc[mi][ni], al[mi], bh[ni]);
                    mma16816(acc[mi][ni], ah[mi], bl[ni]);
                }
        }
    };

    constexpr int nch = KTOT / 32;
    loadG(0);
    storeS(0, 0);
    __syncthreads();
    #pragma unroll
    for (int kc = 0; kc < nch; kc++) {
        if (kc + 1 < nch) loadG((kc + 1) * 32);
        comp(kc & 1);
        if (kc + 1 < nch) {
            storeS((kc + 1) & 1, (kc + 1) * 32);
            __syncthreads();
        }
    }

    // --- epilogue: bias / gather / store + fused per-channel stats
    float fs[8], fq[8];
    #pragma unroll
    for (int i = 0; i < 8; i++) { fs[i] = 0.f; fq[i] = 0.f; }

    #pragma unroll
    for (int mi = 0; mi < 2; mi++) {
        #pragma unroll
        for (int half = 0; half < 2; half++) {
            const int gm = m0 + wm + mi * 16 + half * 8 + lr;
            const float *P0 = nullptr, *P1 = nullptr, *P2 = nullptr;
            float w0 = 0.f, w1 = 0.f, w2 = 0.f;
            if (MODE == 1) {
                const int bb_ = gm >> 14;                // NN = 16384
                int i0 = gidx[gm * 3 + 0], i1 = gidx[gm * 3 + 1], i2 = gidx[gm * 3 + 2];
                w0 = gw[gm * 3 + 0]; w1 = gw[gm * 3 + 1]; w2 = gw[gm * 3 + 2];
                P0 = p2w + ((size_t)bb_ * SS + i0) * O1 + n0;
                P1 = p2w + ((size_t)bb_ * SS + i1) * O1 + n0;
                P2 = p2w + ((size_t)bb_ * SS + i2) * O1 + n0;
            }
            float* Cp = C + (size_t)gm * ldc + n0;
            #pragma unroll
            for (int ni = 0; ni < 4; ni++) {
                const int col = wn + ni * 8 + lc * 2;
                float x = acc[mi][ni][half * 2 + 0];
                float y = acc[mi][ni][half * 2 + 1];
                if (MODE != 0) { x += sbias[col]; y += sbias[col + 1]; }
                if (MODE == 1) {
                    float2 q0 = *(const float2*)(P0 + col);
                    float2 q1 = *(const float2*)(P1 + col);
                    float2 q2 = *(const float2*)(P2 + col);
                    x += w0 * q0.x + w1 * q1.x + w2 * q2.x;
                    y += w0 * q0.y + w1 * q1.y + w2 * q2.y;
                }
                if (MODE != 0) {
                    fs[ni * 2 + 0] += x; fq[ni * 2 + 0] = fmaf(x, x, fq[ni * 2 + 0]);
                    fs[ni * 2 + 1] += y; fq[ni * 2 + 1] = fmaf(y, y, fq[ni * 2 + 1]);
                }
                *(float2*)(Cp + col) = make_float2(x, y);
            }
        }
    }

    if (MODE != 0) {
        #pragma unroll
        for (int i = 0; i < 8; i++) {
            fs[i] += __shfl_xor_sync(0xFFFFFFFFu, fs[i], 4);
            fs[i] += __shfl_xor_sync(0xFFFFFFFFu, fs[i], 8);
            fs[i] += __shfl_xor_sync(0xFFFFFFFFu, fs[i], 16);
            fq[i] += __shfl_xor_sync(0xFFFFFFFFu, fq[i], 4);
            fq[i] += __shfl_xor_sync(0xFFFFFFFFu, fq[i], 8);
            fq[i] += __shfl_xor_sync(0xFFFFFFFFu, fq[i], 16);
        }
        if (lr == 0) {
            #pragma unroll
            for (int ni = 0; ni < 4; ni++) {
                int col = wn + ni * 8 + lc * 2;
                atomicAdd(&ssum[col],     fs[ni * 2 + 0]);
                atomicAdd(&ssum[col + 1], fs[ni * 2 + 1]);
                atomicAdd(&ssq[col],      fq[ni * 2 + 0]);
                atomicAdd(&ssq[col + 1],  fq[ni * 2 + 1]);
            }
        }
        __syncthreads();
        if (tid < 64) {
            atomicAdd(&gsum[n0 + tid], ssum[tid]);
            atomicAdd(&gsq[n0 + tid],  ssq[tid]);
        }
    }
}

// ---------------------------------------------------------------------------
__global__ void finalize_kernel(const float* __restrict__ sum, const float* __restrict__ sq,
                                const float* __restrict__ gamma, const float* __restrict__ beta,
                                float* __restrict__ a_out, float* __restrict__ c_out)
{
    const int c = threadIdx.x;
    const float Minv = 1.f / (float)MTOT;
    float mean = sum[c] * Minv;
    float var  = fmaf(-mean, mean, sq[c] * Minv);
    float s = gamma[c] * rsqrtf(var + 1e-5f);
    a_out[c] = s;
    c_out[c] = fmaf(-mean, s, beta[c]);
}

__global__ void bnrelu_kernel(float* __restrict__ out,
                              const float* __restrict__ a, const float* __restrict__ c)
{
    const size_t i = (size_t)blockIdx.x * blockDim.x + threadIdx.x;
    float4 v = ((float4*)out)[i];
    const int cb = (int)((i * 4) & (O2 - 1));
    v.x = fmaxf(fmaf(v.x, a[cb + 0], c[cb + 0]), 0.f);
    v.y = fmaxf(fmaf(v.y, a[cb + 1], c[cb + 1]), 0.f);
    v.z = fmaxf(fmaf(v.z, a[cb + 2], c[cb + 2]), 0.f);
    v.w = fmaxf(fmaf(v.w, a[cb + 3], c[cb + 3]), 0.f);
    ((float4*)out)[i] = v;
}

// ---------------------------------------------------------------------------
extern "C" void kernel_launch(void* const* d_in, const int* in_sizes, int n_in,
                              void* d_out, int out_size)
{
    const float* xyz1    = (const float*)d_in[0];
    const float* xyz2    = (const float*)d_in[1];
    const float* points1 = (const float*)d_in[2];
    const float* points2 = (const float*)d_in[3];
    const float* W1      = (const float*)d_in[4];
    const float* b1      = (const float*)d_in[5];
    const float* g1      = (const float*)d_in[6];
    const float* be1     = (const float*)d_in[7];
    const float* W2      = (const float*)d_in[8];
    const float* b2      = (const float*)d_in[9];
    const float* g2      = (const float*)d_in[10];
    const float* be2     = (const float*)d_in[11];
    float* out = (float*)d_out;

    float *p2w, *h1, *wp, *sum1, *sq1, *a1, *c1, *sum2, *sq2, *a2, *c2;
    int* idxp;
    __nv_bfloat16 *b0h, *b0l, *b1h, *b1l, *b2h, *b2l;
    cudaGetSymbolAddress((void**)&p2w,  g_p2w);
    cudaGetSymbolAddress((void**)&h1,   g_h1);
    cudaGetSymbolAddress((void**)&idxp, g_idx);
    cudaGetSymbolAddress((void**)&wp,   g_w);
    cudaGetSymbolAddress((void**)&sum1, g_sum1);
    cudaGetSymbolAddress((void**)&sq1,  g_sq1);
    cudaGetSymbolAddress((void**)&a1,   g_a1);
    cudaGetSymbolAddress((void**)&c1,   g_c1);
    cudaGetSymbolAddress((void**)&sum2, g_sum2);
    cudaGetSymbolAddress((void**)&sq2,  g_sq2);
    cudaGetSymbolAddress((void**)&a2,   g_a2);
    cudaGetSymbolAddress((void**)&c2,   g_c2);
    cudaGetSymbolAddress((void**)&b0h,  g_b0h);
    cudaGetSymbolAddress((void**)&b0l,  g_b0l);
    cudaGetSymbolAddress((void**)&b1h,  g_b1h);
    cudaGetSymbolAddress((void**)&b1l,  g_b1l);
    cudaGetSymbolAddress((void**)&b2h,  g_b2h);
    cudaGetSymbolAddress((void**)&b2l,  g_b2l);

    cudaFuncSetAttribute(mma_gemm<0, 256>, cudaFuncAttributeMaxDynamicSharedMemorySize, SM_SZ);
    cudaFuncSetAttribute(mma_gemm<1, 128>, cudaFuncAttributeMaxDynamicSharedMemorySize, SM_SZ);
    cudaFuncSetAttribute(mma_gemm<2, 256>, cudaFuncAttributeMaxDynamicSharedMemorySize, SM_SZ);

    // 1. zero BN accumulators + weight split
    zero_stats_kernel<<<1, 256>>>();
    prep_weights_kernel<<<(O1 * C1) / 256, 256>>>(W1, W2);

    // 2. 3-NN
    knn_kernel<<<dim3(NN / 256, BB), 256>>>(xyz1, xyz2, idxp, wp);

    // 3. P2W = points2 @ W1b^T   [B*S, 256]
    mma_gemm<0, 256><<<dim3(O1 / 64, (BB * SS) / 128), 256, SM_SZ>>>(
        points2, D2, b0h, b0l, p2w, O1,
        nullptr, nullptr, nullptr, nullptr, nullptr, nullptr, nullptr, nullptr);

    // 4. h1 = points1 @ W1a^T + b1 + gather   (BN1 stats fused)
    mma_gemm<1, 128><<<dim3(O1 / 64, MTOT / 128), 256, SM_SZ>>>(
        points1, D1, b1h, b1l, h1, O1,
        b1, nullptr, nullptr, p2w, idxp, wp, sum1, sq1);

    // 5. BN1 coefficients
    finalize_kernel<<<1, O1>>>(sum1, sq1, g1, be1, a1, c1);

    // 6. out = relu(a1*h1 + c1) @ W2^T + b2   (BN2 stats fused)
    mma_gemm<2, 256><<<dim3(O2 / 64, MTOT / 128), 256, SM_SZ>>>(
        h1, O1, b2h, b2l, out, O2,
        b2, a1, c1, nullptr, nullptr, nullptr, sum2, sq2);

    // 7. BN2 coefficients + in-place apply
    finalize_kernel<<<1, O2>>>(sum2, sq2, g2, be2, a2, c2);
    bnrelu_kernel<<<(MTOT * O2 / 4) / 256, 256>>>(out, a2, c2);
}

// round 8
// speedup vs baseline: 1.4790x; 1.0726x over previous
#include <cuda_runtime.h>
#include <cuda_bf16.h>
#include <cstdint>

// Problem constants (PointNetFeaturePropagation_5609227289179)
#define BB   4
#define NN   16384
#define SS   4096
#define D1   128
#define D2   256
#define C1   384
#define O1   256
#define O2   128
#define MTOT (BB*NN)   // 65536

// ---------------------------------------------------------------------------
// Scratch (device globals — no allocation allowed)
// ---------------------------------------------------------------------------
__device__ __align__(16) float g_p2w[BB * SS * O1];   // points2 @ W1b^T [16384,256]
__device__ __align__(16) float g_h1 [MTOT * O1];      // layer1 pre-BN   [65536,256]
__device__ __align__(16) int   g_idx[MTOT * 3];
__device__ __align__(16) float g_w  [MTOT * 3];
__device__ __align__(16) __nv_bfloat16 g_b0h[O1 * D2], g_b0l[O1 * D2];  // W1b split
__device__ __align__(16) __nv_bfloat16 g_b1h[O1 * D1], g_b1l[O1 * D1];  // W1a split
__device__ __align__(16) __nv_bfloat16 g_b2h[O2 * O1], g_b2l[O2 * O1];  // W2 split
__device__ float g_sum1[O1], g_sq1[O1];
__device__ float g_sum2[O2], g_sq2[O2];

// ---------------------------------------------------------------------------
__global__ void zero_stats_kernel() {
    int t = threadIdx.x;
    if (t < O1) { g_sum1[t] = 0.f; g_sq1[t] = 0.f; }
    if (t < O2) { g_sum2[t] = 0.f; g_sq2[t] = 0.f; }
}

// Pre-split weights into bf16 hi/lo
__global__ void prep_weights_kernel(const float* __restrict__ W1,
                                    const float* __restrict__ W2) {
    int idx = blockIdx.x * 256 + threadIdx.x;
    if (idx < O1 * C1) {
        int o = idx / C1, k = idx - o * C1;
        float v = W1[idx];
        __nv_bfloat16 h = __float2bfloat16(v);
        __nv_bfloat16 l = __float2bfloat16(v - __bfloat162float(h));
        if (k < D1) { g_b1h[o * D1 + k] = h; g_b1l[o * D1 + k] = l; }
        else        { g_b0h[o * D2 + k - D1] = h; g_b0l[o * D2 + k - D1] = l; }
    }
    if (idx < O2 * O1) {
        float v = W2[idx];
        __nv_bfloat16 h = __float2bfloat16(v);
        __nv_bfloat16 l = __float2bfloat16(v - __bfloat162float(h));
        g_b2h[idx] = h; g_b2l[idx] = l;
    }
}

// ---------------------------------------------------------------------------
// 3-NN: ordering key d' = ||p||^2 - 2 q.p, with (-2x,-2y,-2z,||p||^2) staged
// in smem -> 3 FMA per candidate. Pairwise fmin pre-filter cuts compare cost;
// the rare-hit path does the exact original in-order insertion.
// ---------------------------------------------------------------------------
__global__ __launch_bounds__(256) void knn_kernel(
    const float* __restrict__ xyz1, const float* __restrict__ xyz2,
    int* __restrict__ oidx, float* __restrict__ ow)
{
    __shared__ float4 sp[2048];
    const int b = blockIdx.y;
    const int n = blockIdx.x * 256 + threadIdx.x;

    const float* q = xyz1 + ((size_t)b * NN + n) * 3;
    const float qx = q[0], qy = q[1], qz = q[2];

    float b0v = 1e30f, b1v = 1e30f, b2v = 1e30f;
    int   i0 = 0, i1 = 0, i2 = 0;

    auto insert = [&](float d, int s) {
        if (d < b2v) {
            if (d < b1v) {
                b2v = b1v; i2 = i1;
                if (d < b0v) { b1v = b0v; i1 = i0; b0v = d; i0 = s; }
                else         { b1v = d;  i1 = s; }
            } else { b2v = d; i2 = s; }
        }
    };

    for (int c0 = 0; c0 < SS; c0 += 2048) {
        __syncthreads();
        #pragma unroll
        for (int r = 0; r < 8; r++) {
            int s = threadIdx.x + r * 256;
            const float* p = xyz2 + ((size_t)b * SS + c0 + s) * 3;
            float x = p[0], y = p[1], z = p[2];
            sp[s] = make_float4(-2.f * x, -2.f * y, -2.f * z, x * x + y * y + z * z);
        }
        __syncthreads();

        #pragma unroll 4
        for (int j = 0; j < 2048; j += 2) {
            float4 p0 = sp[j];
            float4 p1 = sp[j + 1];
            float d0 = fmaf(qx, p0.x, fmaf(qy, p0.y, fmaf(qz, p0.z, p0.w)));
            float d1 = fmaf(qx, p1.x, fmaf(qy, p1.y, fmaf(qz, p1.z, p1.w)));
            if (fminf(d0, d1) < b2v) {
                insert(d0, c0 + j);
                insert(d1, c0 + j + 1);
            }
        }
    }

    const float qn = qx * qx + qy * qy + qz * qz;
    float d0 = fmaxf(b0v + qn, 0.f);
    float d1 = fmaxf(b1v + qn, 0.f);
    float d2 = fmaxf(b2v + qn, 0.f);
    float r0 = 1.f / (d0 + 1e-8f);
    float r1 = 1.f / (d1 + 1e-8f);
    float r2 = 1.f / (d2 + 1e-8f);
    float inv = 1.f / (r0 + r1 + r2);

    size_t o = ((size_t)b * NN + n) * 3;
    oidx[o + 0] = i0; oidx[o + 1] = i1; oidx[o + 2] = i2;
    ow[o + 0] = r0 * inv; ow[o + 1] = r1 * inv; ow[o + 2] = r2 * inv;
}

// ---------------------------------------------------------------------------
// bf16-split tensor-core GEMM via mma.sync.m16n8k16 (proven core):
//   C[M,N] = A[M,K] @ Bw[N,K]^T,  D = Ah*Bh + Al*Bh + Ah*Bl  (fp32 accum)
// CTA tile 128x64, BK=32, 8 warps (4x2) of 32x32. Double-buffered smem.
// MODE 0: plain
// MODE 1: +bias+3NN gather, fused stats out
// MODE 2: BN coeffs computed inline from (gsum_in,gsq_in,gamma,beta);
//         BN+ReLU applied to A on load; +bias; fused stats out
// ---------------------------------------------------------------------------
#define STRB  80          // smem row stride bytes (40 bf16)
#define A_T   10240       // 128*80
#define B_T   5120        // 64*80
#define STGB  30720       // per-stage bytes: Ah,Al,Bh,Bl
#define SM_BIAS 61440
#define SM_SUM  61696
#define SM_SQ   61952
#define SM_SA   62208
#define SM_SC   63232
#define SM_SZ   64256

__device__ __forceinline__ void mma16816(float* d, const uint32_t* a, const uint32_t* b) {
    asm volatile(
        "mma.sync.aligned.m16n8k16.row.col.f32.bf16.bf16.f32 "
        "{%0,%1,%2,%3}, {%4,%5,%6,%7}, {%8,%9}, {%0,%1,%2,%3};"
        : "+f"(d[0]), "+f"(d[1]), "+f"(d[2]), "+f"(d[3])
        : "r"(a[0]), "r"(a[1]), "r"(a[2]), "r"(a[3]), "r"(b[0]), "r"(b[1]));
}
__device__ __forceinline__ uint32_t pack_hi2(float x, float y) {
    uint16_t hx = __bfloat16_as_ushort(__float2bfloat16(x));
    uint16_t hy = __bfloat16_as_ushort(__float2bfloat16(y));
    return (uint32_t)hx | ((uint32_t)hy << 16);
}
__device__ __forceinline__ uint32_t pack_lo2(float x, float y) {
    float hx = __bfloat162float(__float2bfloat16(x));
    float hy = __bfloat162float(__float2bfloat16(y));
    uint16_t lx = __bfloat16_as_ushort(__float2bfloat16(x - hx));
    uint16_t ly = __bfloat16_as_ushort(__float2bfloat16(y - hy));
    return (uint32_t)lx | ((uint32_t)ly << 16);
}

template<int MODE, int KTOT>
__global__ __launch_bounds__(256, 2) void mma_gemm(
    const float* __restrict__ A, int lda,
    const __nv_bfloat16* __restrict__ Bh, const __nv_bfloat16* __restrict__ Bl,
    float* __restrict__ C, int ldc,
    const float* __restrict__ bias,
    const float* __restrict__ gamma, const float* __restrict__ beta,
    const float* __restrict__ gsum_in, const float* __restrict__ gsq_in,
    const float* __restrict__ p2w, const int* __restrict__ gidx,
    const float* __restrict__ gw,
    float* __restrict__ gsum, float* __restrict__ gsq)
{
    extern __shared__ char sm[];
    const int tid = threadIdx.x;
    const int m0 = blockIdx.y * 128;
    const int n0 = blockIdx.x * 64;

    float* sbias = (float*)(sm + SM_BIAS);
    float* ssum  = (float*)(sm + SM_SUM);
    float* ssq   = (float*)(sm + SM_SQ);
    float* sa    = (float*)(sm + SM_SA);
    float* sc    = (float*)(sm + SM_SC);
    if (MODE != 0 && tid < 64) sbias[tid] = bias[n0 + tid];
    if (MODE != 0 && tid < 128) { if (tid < 64) ssum[tid] = 0.f; else ssq[tid - 64] = 0.f; }
    if (MODE == 2 && tid < KTOT) {
        // inline BN coefficient computation (folds the finalize kernel)
        const float Minv = 1.f / (float)MTOT;
        float mean = gsum_in[tid] * Minv;
        float var  = fmaf(-mean, mean, gsq_in[tid] * Minv);
        float s = gamma[tid] * rsqrtf(var + 1e-5f);
        sa[tid] = s;
        sc[tid] = fmaf(-mean, s, beta[tid]);
    }
    __syncthreads();

    // gmem->reg prefetch mapping
    const int ra = tid >> 1, ka = (tid & 1) * 16;   // A: 128 rows x 32 k
    const int rb = tid >> 2, kb2 = (tid & 3) * 8;   // B: 64 rows x 32 k

    float4 av[4];
    uint4 bhv, blv;

    auto loadG = [&](int k0) {
        const float* ap = A + (size_t)(m0 + ra) * lda + k0 + ka;
        #pragma unroll
        for (int i = 0; i < 4; i++) av[i] = *(const float4*)(ap + i * 4);
        bhv = *(const uint4*)(Bh + (size_t)(n0 + rb) * KTOT + k0 + kb2);
        blv = *(const uint4*)(Bl + (size_t)(n0 + rb) * KTOT + k0 + kb2);
    };
    auto storeS = [&](int st, int k0) {
        char* base = sm + st * STGB;
        #pragma unroll
        for (int i = 0; i < 4; i++) {
            float4 v = av[i];
            if (MODE == 2) {
                int kg = k0 + ka + i * 4;
                v.x = fmaxf(fmaf(v.x, sa[kg + 0], sc[kg + 0]), 0.f);
                v.y = fmaxf(fmaf(v.y, sa[kg + 1], sc[kg + 1]), 0.f);
                v.z = fmaxf(fmaf(v.z, sa[kg + 2], sc[kg + 2]), 0.f);
                v.w = fmaxf(fmaf(v.w, sa[kg + 3], sc[kg + 3]), 0.f);
            }
            uint2 h2 = make_uint2(pack_hi2(v.x, v.y), pack_hi2(v.z, v.w));
            uint2 l2 = make_uint2(pack_lo2(v.x, v.y), pack_lo2(v.z, v.w));
            int ob = ra * STRB + (ka + i * 4) * 2;
            *(uint2*)(base + ob)       = h2;
            *(uint2*)(base + A_T + ob) = l2;
        }
        {
            int ob = rb * STRB + kb2 * 2;
            char* bh_ = base + 2 * A_T + ob;
            char* bl_ = base + 2 * A_T + B_T + ob;
            *(uint2*)(bh_)     = make_uint2(bhv.x, bhv.y);
            *(uint2*)(bh_ + 8) = make_uint2(bhv.z, bhv.w);
            *(uint2*)(bl_)     = make_uint2(blv.x, blv.y);
            *(uint2*)(bl_ + 8) = make_uint2(blv.z, blv.w);
        }
    };

    const int wid = tid >> 5, l = tid & 31;
    const int wm = (wid >> 1) * 32, wn = (wid & 1) * 32;
    const int lr = l >> 2, lc = l & 3;

    float acc[2][4][4];
    #pragma unroll
    for (int mi = 0; mi < 2; mi++)
        #pragma unroll
        for (int ni = 0; ni < 4; ni++)
            #pragma unroll
            for (int j = 0; j < 4; j++) acc[mi][ni][j] = 0.f;

    auto comp = [&](int st) {
        const char* base = sm + st * STGB;
        #pragma unroll
        for (int ks = 0; ks < 2; ks++) {
            const int kb = ks * 32 + lc * 4;
            uint32_t ah[2][4], al[2][4], bh[4][2], bl[4][2];
            #pragma unroll
            for (int mi = 0; mi < 2; mi++) {
                const char* p = base + (wm + mi * 16 + lr) * STRB + kb;
                ah[mi][0] = *(const uint32_t*)(p);
                ah[mi][1] = *(const uint32_t*)(p + 8 * STRB);
                ah[mi][2] = *(const uint32_t*)(p + 16);
                ah[mi][3] = *(const uint32_t*)(p + 8 * STRB + 16);
                const char* q = p + A_T;
                al[mi][0] = *(const uint32_t*)(q);
                al[mi][1] = *(const uint32_t*)(q + 8 * STRB);
                al[mi][2] = *(const uint32_t*)(q + 16);
                al[mi][3] = *(const uint32_t*)(q + 8 * STRB + 16);
            }
            #pragma unroll
            for (int ni = 0; ni < 4; ni++) {
                const char* p = base + 2 * A_T + (wn + ni * 8 + lr) * STRB + kb;
                bh[ni][0] = *(const uint32_t*)(p);
                bh[ni][1] = *(const uint32_t*)(p + 16);
                const char* q = p + B_T;
                bl[ni][0] = *(const uint32_t*)(q);
                bl[ni][1] = *(const uint32_t*)(q + 16);
            }
            #pragma unroll
            for (int mi = 0; mi < 2; mi++)
                #pragma unroll
                for (int ni = 0; ni < 4; ni++) {
                    mma16816(acc[mi][ni], ah[mi], bh[ni]);
                    mma16816(acc[mi][ni], al[mi], bh[ni]);
                    mma16816(acc[mi][ni], ah[mi], bl[ni]);
                }
        }
    };

    constexpr int nch = KTOT / 32;
    loadG(0);
    storeS(0, 0);
    __syncthreads();
    #pragma unroll
    for (int kc = 0; kc < nch; kc++) {
        if (kc + 1 < nch) loadG((kc + 1) * 32);
        comp(kc & 1);
        if (kc + 1 < nch) {
            storeS((kc + 1) & 1, (kc + 1) * 32);
            __syncthreads();
        }
    }

    // --- epilogue: bias / gather / store + fused per-channel stats
    float fs[8], fq[8];
    #pragma unroll
    for (int i = 0; i < 8; i++) { fs[i] = 0.f; fq[i] = 0.f; }

    #pragma unroll
    for (int mi = 0; mi < 2; mi++) {
        #pragma unroll
        for (int half = 0; half < 2; half++) {
            const int gm = m0 + wm + mi * 16 + half * 8 + lr;
            const float *P0 = nullptr, *P1 = nullptr, *P2 = nullptr;
            float w0 = 0.f, w1 = 0.f, w2 = 0.f;
            if (MODE == 1) {
                const int bb_ = gm >> 14;                // NN = 16384
                int i0 = gidx[gm * 3 + 0], i1 = gidx[gm * 3 + 1], i2 = gidx[gm * 3 + 2];
                w0 = gw[gm * 3 + 0]; w1 = gw[gm * 3 + 1]; w2 = gw[gm * 3 + 2];
                P0 = p2w + ((size_t)bb_ * SS + i0) * O1 + n0;
                P1 = p2w + ((size_t)bb_ * SS + i1) * O1 + n0;
                P2 = p2w + ((size_t)bb_ * SS + i2) * O1 + n0;
            }
            float* Cp = C + (size_t)gm * ldc + n0;
            #pragma unroll
            for (int ni = 0; ni < 4; ni++) {
                const int col = wn + ni * 8 + lc * 2;
                float x = acc[mi][ni][half * 2 + 0];
                float y = acc[mi][ni][half * 2 + 1];
                if (MODE != 0) { x += sbias[col]; y += sbias[col + 1]; }
                if (MODE == 1) {
                    float2 q0 = *(const float2*)(P0 + col);
                    float2 q1 = *(const float2*)(P1 + col);
                    float2 q2 = *(const float2*)(P2 + col);
                    x += w0 * q0.x + w1 * q1.x + w2 * q2.x;
                    y += w0 * q0.y + w1 * q1.y + w2 * q2.y;
                }
                if (MODE != 0) {
                    fs[ni * 2 + 0] += x; fq[ni * 2 + 0] = fmaf(x, x, fq[ni * 2 + 0]);
                    fs[ni * 2 + 1] += y; fq[ni * 2 + 1] = fmaf(y, y, fq[ni * 2 + 1]);
                }
                *(float2*)(Cp + col) = make_float2(x, y);
            }
        }
    }

    if (MODE != 0) {
        #pragma unroll
        for (int i = 0; i < 8; i++) {
            fs[i] += __shfl_xor_sync(0xFFFFFFFFu, fs[i], 4);
            fs[i] += __shfl_xor_sync(0xFFFFFFFFu, fs[i], 8);
            fs[i] += __shfl_xor_sync(0xFFFFFFFFu, fs[i], 16);
            fq[i] += __shfl_xor_sync(0xFFFFFFFFu, fq[i], 4);
            fq[i] += __shfl_xor_sync(0xFFFFFFFFu, fq[i], 8);
            fq[i] += __shfl_xor_sync(0xFFFFFFFFu, fq[i], 16);
        }
        if (lr == 0) {
            #pragma unroll
            for (int ni = 0; ni < 4; ni++) {
                int col = wn + ni * 8 + lc * 2;
                atomicAdd(&ssum[col],     fs[ni * 2 + 0]);
                atomicAdd(&ssum[col + 1], fs[ni * 2 + 1]);
                atomicAdd(&ssq[col],      fq[ni * 2 + 0]);
                atomicAdd(&ssq[col + 1],  fq[ni * 2 + 1]);
            }
        }
        __syncthreads();
        if (tid < 64) {
            atomicAdd(&gsum[n0 + tid], ssum[tid]);
            atomicAdd(&gsq[n0 + tid],  ssq[tid]);
        }
    }
}

// ---------------------------------------------------------------------------
// Final BN2+ReLU apply, with inline coefficient computation (folds finalize).
// ---------------------------------------------------------------------------
__global__ void bnrelu_kernel(float* __restrict__ out,
                              const float* __restrict__ sum, const float* __restrict__ sq,
                              const float* __restrict__ gamma, const float* __restrict__ beta)
{
    __shared__ float sa[O2], sc[O2];
    const int tid = threadIdx.x;
    if (tid < O2) {
        const float Minv = 1.f / (float)MTOT;
        float mean = sum[tid] * Minv;
        float var  = fmaf(-mean, mean, sq[tid] * Minv);
        float s = gamma[tid] * rsqrtf(var + 1e-5f);
        sa[tid] = s;
        sc[tid] = fmaf(-mean, s, beta[tid]);
    }
    __syncthreads();

    const size_t i = (size_t)blockIdx.x * blockDim.x + tid;
    float4 v = ((float4*)out)[i];
    const int cb = (int)((i * 4) & (O2 - 1));
    v.x = fmaxf(fmaf(v.x, sa[cb + 0], sc[cb + 0]), 0.f);
    v.y = fmaxf(fmaf(v.y, sa[cb + 1], sc[cb + 1]), 0.f);
    v.z = fmaxf(fmaf(v.z, sa[cb + 2], sc[cb + 2]), 0.f);
    v.w = fmaxf(fmaf(v.w, sa[cb + 3], sc[cb + 3]), 0.f);
    ((float4*)out)[i] = v;
}

// ---------------------------------------------------------------------------
extern "C" void kernel_launch(void* const* d_in, const int* in_sizes, int n_in,
                              void* d_out, int out_size)
{
    const float* xyz1    = (const float*)d_in[0];
    const float* xyz2    = (const float*)d_in[1];
    const float* points1 = (const float*)d_in[2];
    const float* points2 = (const float*)d_in[3];
    const float* W1      = (const float*)d_in[4];
    const float* b1      = (const float*)d_in[5];
    const float* g1      = (const float*)d_in[6];
    const float* be1     = (const float*)d_in[7];
    const float* W2      = (const float*)d_in[8];
    const float* b2      = (const float*)d_in[9];
    const float* g2      = (const float*)d_in[10];
    const float* be2     = (const float*)d_in[11];
    float* out = (float*)d_out;

    float *p2w, *h1, *wp, *sum1, *sq1, *sum2, *sq2;
    int* idxp;
    __nv_bfloat16 *b0h, *b0l, *b1h, *b1l, *b2h, *b2l;
    cudaGetSymbolAddress((void**)&p2w,  g_p2w);
    cudaGetSymbolAddress((void**)&h1,   g_h1);
    cudaGetSymbolAddress((void**)&idxp, g_idx);
    cudaGetSymbolAddress((void**)&wp,   g_w);
    cudaGetSymbolAddress((void**)&sum1, g_sum1);
    cudaGetSymbolAddress((void**)&sq1,  g_sq1);
    cudaGetSymbolAddress((void**)&sum2, g_sum2);
    cudaGetSymbolAddress((void**)&sq2,  g_sq2);
    cudaGetSymbolAddress((void**)&b0h,  g_b0h);
    cudaGetSymbolAddress((void**)&b0l,  g_b0l);
    cudaGetSymbolAddress((void**)&b1h,  g_b1h);
    cudaGetSymbolAddress((void**)&b1l,  g_b1l);
    cudaGetSymbolAddress((void**)&b2h,  g_b2h);
    cudaGetSymbolAddress((void**)&b2l,  g_b2l);

    cudaFuncSetAttribute(mma_gemm<0, 256>, cudaFuncAttributeMaxDynamicSharedMemorySize, SM_SZ);
    cudaFuncSetAttribute(mma_gemm<1, 128>, cudaFuncAttributeMaxDynamicSharedMemorySize, SM_SZ);
    cudaFuncSetAttribute(mma_gemm<2, 256>, cudaFuncAttributeMaxDynamicSharedMemorySize, SM_SZ);

    // Side stream + events for knn overlap (created per call, intentionally
    // leaked: kernel_launch runs only a handful of times, and destroying
    // capture-participating handles mid-capture is illegal).
    cudaStream_t s1;
    cudaEvent_t evFork, evJoin;
    cudaStreamCreateWithFlags(&s1, cudaStreamNonBlocking);
    cudaEventCreateWithFlags(&evFork, cudaEventDisableTiming);
    cudaEventCreateWithFlags(&evJoin, cudaEventDisableTiming);

    // Fork: knn runs on s1 concurrently with zero/prep/gemm0 on the main stream.
    cudaEventRecord(evFork, 0);
    cudaStreamWaitEvent(s1, evFork, 0);
    knn_kernel<<<dim3(NN / 256, BB), 256, 0, s1>>>(xyz1, xyz2, idxp, wp);
    cudaEventRecord(evJoin, s1);

    // Main stream: zero BN accumulators, weight split, P2W GEMM.
    zero_stats_kernel<<<1, 256>>>();
    prep_weights_kernel<<<(O1 * C1) / 256, 256>>>(W1, W2);
    mma_gemm<0, 256><<<dim3(O1 / 64, (BB * SS) / 128), 256, SM_SZ>>>(
        points2, D2, b0h, b0l, p2w, O1,
        nullptr, nullptr, nullptr, nullptr, nullptr, nullptr, nullptr, nullptr,
        nullptr, nullptr);

    // Join: gemm1 needs knn results.
    cudaStreamWaitEvent(0, evJoin, 0);

    // gemm1: h1 = points1 @ W1a^T + b1 + gather   (BN1 stats fused)
    mma_gemm<1, 128><<<dim3(O1 / 64, MTOT / 128), 256, SM_SZ>>>(
        points1, D1, b1h, b1l, h1, O1,
        b1, nullptr, nullptr, nullptr, nullptr, p2w, idxp, wp, sum1, sq1);

    // gemm2: out = relu(bn1(h1)) @ W2^T + b2   (BN1 coeffs inline, BN2 stats fused)
    mma_gemm<2, 256><<<dim3(O2 / 64, MTOT / 128), 256, SM_SZ>>>(
        h1, O1, b2h, b2l, out, O2,
        b2, g1, be1, sum1, sq1, nullptr, nullptr, nullptr, sum2, sq2);

    // BN2 + ReLU in place (coeffs inline)
    bnrelu_kernel<<<(MTOT * O2 / 4) / 256, 256>>>(out, sum2, sq2, g2, be2);
}

// round 10
// speedup vs baseline: 1.5365x; 1.0389x over previous
#include <cuda_runtime.h>
#include <cuda_bf16.h>
#include <cstdint>

// Problem constants (PointNetFeaturePropagation_5609227289179)
#define BB   4
#define NN   16384
#define SS   4096
#define D1   128
#define D2   256
#define C1   384
#define O1   256
#define O2   128
#define MTOT (BB*NN)   // 65536

// ---------------------------------------------------------------------------
// Scratch (device globals — no allocation allowed)
// ---------------------------------------------------------------------------
__device__ __align__(16) float g_p2w[BB * SS * O1];   // points2 @ W1b^T [16384,256]
__device__ __align__(16) float g_h1 [MTOT * O1];      // layer1 pre-BN   [65536,256]
__device__ __align__(16) int   g_idx[MTOT * 3];
__device__ __align__(16) float g_w  [MTOT * 3];
__device__ __align__(16) __nv_bfloat16 g_b0h[O1 * D2], g_b0l[O1 * D2];  // W1b split
__device__ __align__(16) __nv_bfloat16 g_b1h[O1 * D1], g_b1l[O1 * D1];  // W1a split
__device__ __align__(16) __nv_bfloat16 g_b2h[O2 * O1], g_b2l[O2 * O1];  // W2 split
__device__ float g_sum1[O1], g_sq1[O1];
__device__ float g_sum2[O2], g_sq2[O2];

// ---------------------------------------------------------------------------
__global__ void zero_stats_kernel() {
    int t = threadIdx.x;
    if (t < O1) { g_sum1[t] = 0.f; g_sq1[t] = 0.f; }
    if (t < O2) { g_sum2[t] = 0.f; g_sq2[t] = 0.f; }
}

// Pre-split weights into bf16 hi/lo
__global__ void prep_weights_kernel(const float* __restrict__ W1,
                                    const float* __restrict__ W2) {
    int idx = blockIdx.x * 256 + threadIdx.x;
    if (idx < O1 * C1) {
        int o = idx / C1, k = idx - o * C1;
        float v = W1[idx];
        __nv_bfloat16 h = __float2bfloat16(v);
        __nv_bfloat16 l = __float2bfloat16(v - __bfloat162float(h));
        if (k < D1) { g_b1h[o * D1 + k] = h; g_b1l[o * D1 + k] = l; }
        else        { g_b0h[o * D2 + k - D1] = h; g_b0l[o * D2 + k - D1] = l; }
    }
    if (idx < O2 * O1) {
        float v = W2[idx];
        __nv_bfloat16 h = __float2bfloat16(v);
        __nv_bfloat16 l = __float2bfloat16(v - __bfloat162float(h));
        g_b2h[idx] = h; g_b2l[idx] = l;
    }
}

// ---------------------------------------------------------------------------
// 3-NN: ordering key d' = ||p||^2 - 2 q.p, with (-2x,-2y,-2z,||p||^2) staged
// in smem -> 3 FMA per candidate. Pairwise fmin pre-filter cuts compare cost.
// ---------------------------------------------------------------------------
__global__ __launch_bounds__(256) void knn_kernel(
    const float* __restrict__ xyz1, const float* __restrict__ xyz2,
    int* __restrict__ oidx, float* __restrict__ ow)
{
    __shared__ float4 sp[2048];
    const int b = blockIdx.y;
    const int n = blockIdx.x * 256 + threadIdx.x;

    const float* q = xyz1 + ((size_t)b * NN + n) * 3;
    const float qx = q[0], qy = q[1], qz = q[2];

    float b0v = 1e30f, b1v = 1e30f, b2v = 1e30f;
    int   i0 = 0, i1 = 0, i2 = 0;

    auto insert = [&](float d, int s) {
        if (d < b2v) {
            if (d < b1v) {
                b2v = b1v; i2 = i1;
                if (d < b0v) { b1v = b0v; i1 = i0; b0v = d; i0 = s; }
                else         { b1v = d;  i1 = s; }
            } else { b2v = d; i2 = s; }
        }
    };

    for (int c0 = 0; c0 < SS; c0 += 2048) {
        __syncthreads();
        #pragma unroll
        for (int r = 0; r < 8; r++) {
            int s = threadIdx.x + r * 256;
            const float* p = xyz2 + ((size_t)b * SS + c0 + s) * 3;
            float x = p[0], y = p[1], z = p[2];
            sp[s] = make_float4(-2.f * x, -2.f * y, -2.f * z, x * x + y * y + z * z);
        }
        __syncthreads();

        #pragma unroll 4
        for (int j = 0; j < 2048; j += 2) {
            float4 p0 = sp[j];
            float4 p1 = sp[j + 1];
            float d0 = fmaf(qx, p0.x, fmaf(qy, p0.y, fmaf(qz, p0.z, p0.w)));
            float d1 = fmaf(qx, p1.x, fmaf(qy, p1.y, fmaf(qz, p1.z, p1.w)));
            if (fminf(d0, d1) < b2v) {
                insert(d0, c0 + j);
                insert(d1, c0 + j + 1);
            }
        }
    }

    const float qn = qx * qx + qy * qy + qz * qz;
    float d0 = fmaxf(b0v + qn, 0.f);
    float d1 = fmaxf(b1v + qn, 0.f);
    float d2 = fmaxf(b2v + qn, 0.f);
    float r0 = 1.f / (d0 + 1e-8f);
    float r1 = 1.f / (d1 + 1e-8f);
    float r2 = 1.f / (d2 + 1e-8f);
    float inv = 1.f / (r0 + r1 + r2);

    size_t o = ((size_t)b * NN + n) * 3;
    oidx[o + 0] = i0; oidx[o + 1] = i1; oidx[o + 2] = i2;
    ow[o + 0] = r0 * inv; ow[o + 1] = r1 * inv; ow[o + 2] = r2 * inv;
}

// ---------------------------------------------------------------------------
// bf16-split tensor-core GEMM via mma.sync.m16n8k16:
//   C[M,N] = A[M,K] @ Bw[N,K]^T,  D = Ah*Bh + Al*Bh + Ah*Bl  (fp32 accum)
// CTA tile 128x64, BK=32, 8 warps (4x2) of 32x32. Double-buffered smem.
// Fragment loads via ldmatrix.x4 (ONLY change vs the proven R7 core; layout
// identical, values identical, MMA order identical).
// MODE 0: plain
// MODE 1: +bias+3NN gather, fused stats out
// MODE 2: BN coeffs computed inline from (gsum_in,gsq_in,gamma,beta);
//         BN+ReLU applied to A on load; +bias; fused stats out
// ---------------------------------------------------------------------------
#define STRB  80          // smem row stride bytes (40 bf16)
#define A_T   10240       // 128*80
#define B_T   5120        // 64*80
#define STGB  30720       // per-stage bytes: Ah,Al,Bh,Bl
#define SM_BIAS 61440
#define SM_SUM  61696
#define SM_SQ   61952
#define SM_SA   62208
#define SM_SC   63232
#define SM_SZ   64256

__device__ __forceinline__ void mma16816(float* d, const uint32_t* a, const uint32_t* b) {
    asm volatile(
        "mma.sync.aligned.m16n8k16.row.col.f32.bf16.bf16.f32 "
        "{%0,%1,%2,%3}, {%4,%5,%6,%7}, {%8,%9}, {%0,%1,%2,%3};"
        : "+f"(d[0]), "+f"(d[1]), "+f"(d[2]), "+f"(d[3])
        : "r"(a[0]), "r"(a[1]), "r"(a[2]), "r"(a[3]), "r"(b[0]), "r"(b[1]));
}
__device__ __forceinline__ void ldsm4(uint32_t* r, uint32_t addr) {
    asm volatile("ldmatrix.sync.aligned.m8n8.x4.shared.b16 {%0,%1,%2,%3}, [%4];"
        : "=r"(r[0]), "=r"(r[1]), "=r"(r[2]), "=r"(r[3]) : "r"(addr));
}
__device__ __forceinline__ uint32_t smem_u32(const void* p) {
    uint32_t a;
    asm("{ .reg .u64 t; cvta.to.shared.u64 t, %1; cvt.u32.u64 %0, t; }" : "=r"(a) : "l"(p));
    return a;
}
__device__ __forceinline__ uint32_t pack_hi2(float x, float y) {
    uint16_t hx = __bfloat16_as_ushort(__float2bfloat16(x));
    uint16_t hy = __bfloat16_as_ushort(__float2bfloat16(y));
    return (uint32_t)hx | ((uint32_t)hy << 16);
}
__device__ __forceinline__ uint32_t pack_lo2(float x, float y) {
    float hx = __bfloat162float(__float2bfloat16(x));
    float hy = __bfloat162float(__float2bfloat16(y));
    uint16_t lx = __bfloat16_as_ushort(__float2bfloat16(x - hx));
    uint16_t ly = __bfloat16_as_ushort(__float2bfloat16(y - hy));
    return (uint32_t)lx | ((uint32_t)ly << 16);
}

template<int MODE, int KTOT>
__global__ __launch_bounds__(256, 2) void mma_gemm(
    const float* __restrict__ A, int lda,
    const __nv_bfloat16* __restrict__ Bh, const __nv_bfloat16* __restrict__ Bl,
    float* __restrict__ C, int ldc,
    const float* __restrict__ bias,
    const float* __restrict__ gamma, const float* __restrict__ beta,
    const float* __restrict__ gsum_in, const float* __restrict__ gsq_in,
    const float* __restrict__ p2w, const int* __restrict__ gidx,
    const float* __restrict__ gw,
    float* __restrict__ gsum, float* __restrict__ gsq)
{
    extern __shared__ char sm[];
    const uint32_t sbase = smem_u32(sm);
    const int tid = threadIdx.x;
    const int m0 = blockIdx.y * 128;
    const int n0 = blockIdx.x * 64;

    float* sbias = (float*)(sm + SM_BIAS);
    float* ssum  = (float*)(sm + SM_SUM);
    float* ssq   = (float*)(sm + SM_SQ);
    float* sa    = (float*)(sm + SM_SA);
    float* sc    = (float*)(sm + SM_SC);
    if (MODE != 0 && tid < 64) sbias[tid] = bias[n0 + tid];
    if (MODE != 0 && tid < 128) { if (tid < 64) ssum[tid] = 0.f; else ssq[tid - 64] = 0.f; }
    if (MODE == 2 && tid < KTOT) {
        const float Minv = 1.f / (float)MTOT;
        float mean = gsum_in[tid] * Minv;
        float var  = fmaf(-mean, mean, gsq_in[tid] * Minv);
        float s = gamma[tid] * rsqrtf(var + 1e-5f);
        sa[tid] = s;
        sc[tid] = fmaf(-mean, s, beta[tid]);
    }
    __syncthreads();

    // gmem->reg prefetch mapping
    const int ra = tid >> 1, ka = (tid & 1) * 16;   // A: 128 rows x 32 k
    const int rb = tid >> 2, kb2 = (tid & 3) * 8;   // B: 64 rows x 32 k

    float4 av[4];
    uint4 bhv, blv;

    auto loadG = [&](int k0) {
        const float* ap = A + (size_t)(m0 + ra) * lda + k0 + ka;
        #pragma unroll
        for (int i = 0; i < 4; i++) av[i] = *(const float4*)(ap + i * 4);
        bhv = *(const uint4*)(Bh + (size_t)(n0 + rb) * KTOT + k0 + kb2);
        blv = *(const uint4*)(Bl + (size_t)(n0 + rb) * KTOT + k0 + kb2);
    };
    auto storeS = [&](int st, int k0) {
        char* base = sm + st * STGB;
        #pragma unroll
        for (int i = 0; i < 4; i++) {
            float4 v = av[i];
            if (MODE == 2) {
                int kg = k0 + ka + i * 4;
                v.x = fmaxf(fmaf(v.x, sa[kg + 0], sc[kg + 0]), 0.f);
                v.y = fmaxf(fmaf(v.y, sa[kg + 1], sc[kg + 1]), 0.f);
                v.z = fmaxf(fmaf(v.z, sa[kg + 2], sc[kg + 2]), 0.f);
                v.w = fmaxf(fmaf(v.w, sa[kg + 3], sc[kg + 3]), 0.f);
            }
            uint2 h2 = make_uint2(pack_hi2(v.x, v.y), pack_hi2(v.z, v.w));
            uint2 l2 = make_uint2(pack_lo2(v.x, v.y), pack_lo2(v.z, v.w));
            int ob = ra * STRB + (ka + i * 4) * 2;
            *(uint2*)(base + ob)       = h2;
            *(uint2*)(base + A_T + ob) = l2;
        }
        {
            int ob = rb * STRB + kb2 * 2;
            char* bh_ = base + 2 * A_T + ob;
            char* bl_ = base + 2 * A_T + B_T + ob;
            *(uint2*)(bh_)     = make_uint2(bhv.x, bhv.y);
            *(uint2*)(bh_ + 8) = make_uint2(bhv.z, bhv.w);
            *(uint2*)(bl_)     = make_uint2(blv.x, blv.y);
            *(uint2*)(bl_ + 8) = make_uint2(blv.z, blv.w);
        }
    };

    const int wid = tid >> 5, l = tid & 31;
    const int wm = (wid >> 1) * 32, wn = (wid & 1) * 32;
    const int lr = l >> 2, lc = l & 3;

    float acc[2][4][4];
    #pragma unroll
    for (int mi = 0; mi < 2; mi++)
        #pragma unroll
        for (int ni = 0; ni < 4; ni++)
            #pragma unroll
            for (int j = 0; j < 4; j++) acc[mi][ni][j] = 0.f;

    // ldmatrix per-lane base addresses (within stage 0):
    //   A: lanes 0-7 -> rows wm+0..7 k-lo (m0=a0), 8-15 -> rows 8..15 k-lo (m1=a1),
    //      16-23 -> rows 0..7 k-hi (m2=a2), 24-31 -> rows 8..15 k-hi (m3=a3).
    //   B: lanes 0-7 -> n wn+0..7 k-lo (b0 of n-octet0), 8-15 -> same rows k-hi (b1),
    //      16-23/24-31 -> n wn+8..15 k-lo/k-hi (b0/b1 of n-octet1).
    const uint32_t a_lane = sbase +
        (uint32_t)((wm + (l & 15)) * STRB + (l >> 4) * 16);
    const uint32_t b_lane = sbase +
        (uint32_t)(2 * A_T + (wn + (l & 7) + ((l >> 4) & 1) * 8) * STRB + ((l >> 3) & 1) * 16);

    auto comp = [&](int st) {
        const uint32_t ab = a_lane + st * STGB;
        const uint32_t bb = b_lane + st * STGB;
        #pragma unroll
        for (int ks = 0; ks < 2; ks++) {
            uint32_t ah[2][4], al[2][4], bh[2][4], bl[2][4];
            #pragma unroll
            for (int mi = 0; mi < 2; mi++) {
                uint32_t a = ab + mi * (16 * STRB) + ks * 32;
                ldsm4(ah[mi], a);
                ldsm4(al[mi], a + A_T);
            }
            #pragma unroll
            for (int ni2 = 0; ni2 < 2; ni2++) {
                uint32_t b = bb + ni2 * (16 * STRB) + ks * 32;
                ldsm4(bh[ni2], b);
                ldsm4(bl[ni2], b + B_T);
            }
            #pragma unroll
            for (int mi = 0; mi < 2; mi++)
                #pragma unroll
                for (int ni = 0; ni < 4; ni++) {
                    const uint32_t* bhf = &bh[ni >> 1][(ni & 1) * 2];
                    const uint32_t* blf = &bl[ni >> 1][(ni & 1) * 2];
                    mma16816(acc[mi][ni], ah[mi], bhf);
                    mma16816(acc[mi][ni], al[mi], bhf);
                    mma16816(acc[mi][ni], ah[mi], blf);
                }
        }
    };

    constexpr int nch = KTOT / 32;
    loadG(0);
    storeS(0, 0);
    __syncthreads();
    #pragma unroll
    for (int kc = 0; kc < nch; kc++) {
        if (kc + 1 < nch) loadG((kc + 1) * 32);
        comp(kc & 1);
        if (kc + 1 < nch) {
            storeS((kc + 1) & 1, (kc + 1) * 32);
            __syncthreads();
        }
    }

    // --- epilogue: bias / gather / store + fused per-channel stats
    float fs[8], fq[8];
    #pragma unroll
    for (int i = 0; i < 8; i++) { fs[i] = 0.f; fq[i] = 0.f; }

    #pragma unroll
    for (int mi = 0; mi < 2; mi++) {
        #pragma unroll
        for (int half = 0; half < 2; half++) {
            const int gm = m0 + wm + mi * 16 + half * 8 + lr;
            const float *P0 = nullptr, *P1 = nullptr, *P2 = nullptr;
            float w0 = 0.f, w1 = 0.f, w2 = 0.f;
            if (MODE == 1) {
                const int bb_ = gm >> 14;                // NN = 16384
                int i0 = gidx[gm * 3 + 0], i1 = gidx[gm * 3 + 1], i2 = gidx[gm * 3 + 2];
                w0 = gw[gm * 3 + 0]; w1 = gw[gm * 3 + 1]; w2 = gw[gm * 3 + 2];
                P0 = p2w + ((size_t)bb_ * SS + i0) * O1 + n0;
                P1 = p2w + ((size_t)bb_ * SS + i1) * O1 + n0;
                P2 = p2w + ((size_t)bb_ * SS + i2) * O1 + n0;
            }
            float* Cp = C + (size_t)gm * ldc + n0;
            #pragma unroll
            for (int ni = 0; ni < 4; ni++) {
                const int col = wn + ni * 8 + lc * 2;
                float x = acc[mi][ni][half * 2 + 0];
                float y = acc[mi][ni][half * 2 + 1];
                if (MODE != 0) { x += sbias[col]; y += sbias[col + 1]; }
                if (MODE == 1) {
                    float2 q0 = *(const float2*)(P0 + col);
                    float2 q1 = *(const float2*)(P1 + col);
                    float2 q2 = *(const float2*)(P2 + col);
                    x += w0 * q0.x + w1 * q1.x + w2 * q2.x;
                    y += w0 * q0.y + w1 * q1.y + w2 * q2.y;
                }
                if (MODE != 0) {
                    fs[ni * 2 + 0] += x; fq[ni * 2 + 0] = fmaf(x, x, fq[ni * 2 + 0]);
                    fs[ni * 2 + 1] += y; fq[ni * 2 + 1] = fmaf(y, y, fq[ni * 2 + 1]);
                }
                *(float2*)(Cp + col) = make_float2(x, y);
            }
        }
    }

    if (MODE != 0) {
        #pragma unroll
        for (int i = 0; i < 8; i++) {
            fs[i] += __shfl_xor_sync(0xFFFFFFFFu, fs[i], 4);
            fs[i] += __shfl_xor_sync(0xFFFFFFFFu, fs[i], 8);
            fs[i] += __shfl_xor_sync(0xFFFFFFFFu, fs[i], 16);
            fq[i] += __shfl_xor_sync(0xFFFFFFFFu, fq[i], 4);
            fq[i] += __shfl_xor_sync(0xFFFFFFFFu, fq[i], 8);
            fq[i] += __shfl_xor_sync(0xFFFFFFFFu, fq[i], 16);
        }
        if (lr == 0) {
            #pragma unroll
            for (int ni = 0; ni < 4; ni++) {
                int col = wn + ni * 8 + lc * 2;
                atomicAdd(&ssum[col],     fs[ni * 2 + 0]);
                atomicAdd(&ssum[col + 1], fs[ni * 2 + 1]);
                atomicAdd(&ssq[col],      fq[ni * 2 + 0]);
                atomicAdd(&ssq[col + 1],  fq[ni * 2 + 1]);
            }
        }
        __syncthreads();
        if (tid < 64) {
            atomicAdd(&gsum[n0 + tid], ssum[tid]);
            atomicAdd(&gsq[n0 + tid],  ssq[tid]);
        }
    }
}

// ---------------------------------------------------------------------------
// Final BN2+ReLU apply, with inline coefficient computation.
// ---------------------------------------------------------------------------
__global__ void bnrelu_kernel(float* __restrict__ out,
                              const float* __restrict__ sum, const float* __restrict__ sq,
                              const float* __restrict__ gamma, const float* __restrict__ beta)
{
    __shared__ float sa[O2], sc[O2];
    const int tid = threadIdx.x;
    if (tid < O2) {
        const float Minv = 1.f / (float)MTOT;
        float mean = sum[tid] * Minv;
        float var  = fmaf(-mean, mean, sq[tid] * Minv);
        float s = gamma[tid] * rsqrtf(var + 1e-5f);
        sa[tid] = s;
        sc[tid] = fmaf(-mean, s, beta[tid]);
    }
    __syncthreads();

    const size_t i = (size_t)blockIdx.x * blockDim.x + tid;
    float4 v = ((float4*)out)[i];
    const int cb = (int)((i * 4) & (O2 - 1));
    v.x = fmaxf(fmaf(v.x, sa[cb + 0], sc[cb + 0]), 0.f);
    v.y = fmaxf(fmaf(v.y, sa[cb + 1], sc[cb + 1]), 0.f);
    v.z = fmaxf(fmaf(v.z, sa[cb + 2], sc[cb + 2]), 0.f);
    v.w = fmaxf(fmaf(v.w, sa[cb + 3], sc[cb + 3]), 0.f);
    ((float4*)out)[i] = v;
}

// ---------------------------------------------------------------------------
extern "C" void kernel_launch(void* const* d_in, const int* in_sizes, int n_in,
                              void* d_out, int out_size)
{
    const float* xyz1    = (const float*)d_in[0];
    const float* xyz2    = (const float*)d_in[1];
    const float* points1 = (const float*)d_in[2];
    const float* points2 = (const float*)d_in[3];
    const float* W1      = (const float*)d_in[4];
    const float* b1      = (const float*)d_in[5];
    const float* g1      = (const float*)d_in[6];
    const float* be1     = (const float*)d_in[7];
    const float* W2      = (const float*)d_in[8];
    const float* b2      = (const float*)d_in[9];
    const float* g2      = (const float*)d_in[10];
    const float* be2     = (const float*)d_in[11];
    float* out = (float*)d_out;

    float *p2w, *h1, *wp, *sum1, *sq1, *sum2, *sq2;
    int* idxp;
    __nv_bfloat16 *b0h, *b0l, *b1h, *b1l, *b2h, *b2l;
    cudaGetSymbolAddress((void**)&p2w,  g_p2w);
    cudaGetSymbolAddress((void**)&h1,   g_h1);
    cudaGetSymbolAddress((void**)&idxp, g_idx);
    cudaGetSymbolAddress((void**)&wp,   g_w);
    cudaGetSymbolAddress((void**)&sum1, g_sum1);
    cudaGetSymbolAddress((void**)&sq1,  g_sq1);
    cudaGetSymbolAddress((void**)&sum2, g_sum2);
    cudaGetSymbolAddress((void**)&sq2,  g_sq2);
    cudaGetSymbolAddress((void**)&b0h,  g_b0h);
    cudaGetSymbolAddress((void**)&b0l,  g_b0l);
    cudaGetSymbolAddress((void**)&b1h,  g_b1h);
    cudaGetSymbolAddress((void**)&b1l,  g_b1l);
    cudaGetSymbolAddress((void**)&b2h,  g_b2h);
    cudaGetSymbolAddress((void**)&b2l,  g_b2l);

    cudaFuncSetAttribute(mma_gemm<0, 256>, cudaFuncAttributeMaxDynamicSharedMemorySize, SM_SZ);
    cudaFuncSetAttribute(mma_gemm<1, 128>, cudaFuncAttributeMaxDynamicSharedMemorySize, SM_SZ);
    cudaFuncSetAttribute(mma_gemm<2, 256>, cudaFuncAttributeMaxDynamicSharedMemorySize, SM_SZ);

    // Side stream + events for knn overlap (created per call, intentionally
    // leaked: only a handful of invocations, and handles participate in capture).
    cudaStream_t s1;
    cudaEvent_t evFork, evJoin;
    cudaStreamCreateWithFlags(&s1, cudaStreamNonBlocking);
    cudaEventCreateWithFlags(&evFork, cudaEventDisableTiming);
    cudaEventCreateWithFlags(&evJoin, cudaEventDisableTiming);

    // Fork: knn runs on s1 concurrently with zero/prep/gemm0.
    cudaEventRecord(evFork, 0);
    cudaStreamWaitEvent(s1, evFork, 0);
    knn_kernel<<<dim3(NN / 256, BB), 256, 0, s1>>>(xyz1, xyz2, idxp, wp);
    cudaEventRecord(evJoin, s1);

    // Main stream: zero BN accumulators, weight split, P2W GEMM.
    zero_stats_kernel<<<1, 256>>>();
    prep_weights_kernel<<<(O1 * C1) / 256, 256>>>(W1, W2);
    mma_gemm<0, 256><<<dim3(O1 / 64, (BB * SS) / 128), 256, SM_SZ>>>(
        points2, D2, b0h, b0l, p2w, O1,
        nullptr, nullptr, nullptr, nullptr, nullptr, nullptr, nullptr, nullptr,
        nullptr, nullptr);

    // Join: gemm1 needs knn results.
    cudaStreamWaitEvent(0, evJoin, 0);

    // gemm1: h1 = points1 @ W1a^T + b1 + gather   (BN1 stats fused)
    mma_gemm<1, 128><<<dim3(O1 / 64, MTOT / 128), 256, SM_SZ>>>(
        points1, D1, b1h, b1l, h1, O1,
        b1, nullptr, nullptr, nullptr, nullptr, p2w, idxp, wp, sum1, sq1);

    // gemm2: out = relu(bn1(h1)) @ W2^T + b2   (BN1 coeffs inline, BN2 stats fused)
    mma_gemm<2, 256><<<dim3(O2 / 64, MTOT / 128), 256, SM_SZ>>>(
        h1, O1, b2h, b2l, out, O2,
        b2, g1, be1, sum1, sq1, nullptr, nullptr, nullptr, sum2, sq2);

    // BN2 + ReLU in place (coeffs inline)
    bnrelu_kernel<<<(MTOT * O2 / 4) / 256, 256>>>(out, sum2, sq2, g2, be2);
}